// round 3
// baseline (speedup 1.0000x reference)
#include <cuda_runtime.h>
#include <math.h>

#define B_ 4
#define S_ 2048
#define D_ 1024
#define H_ 16
#define HD_ 64
#define M_ (B_*S_)      // 8192 rows
#define N_QKV 3072

// Scratch (device globals: allocation-free per harness rules)
__device__ float g_q[B_*H_*S_*HD_];
__device__ float g_k[B_*H_*S_*HD_];
__device__ float g_v[B_*H_*S_*HD_];
__device__ float g_y[B_*S_*D_];

// ---------------------------------------------------------------------------
// SGEMM: C[M x N] = A[M x 1024] @ W[1024 x N] + bias, 128x128x16 tile,
// 256 threads, 8x8 per-thread microtile.
// QKV=true:    epilogue scatters into g_q/g_k/g_v ([B,H,S,HD]).
// A_FROM_GY:   A is taken from device-global g_y INSIDE device code.
//              (Passing g_y from host code passes the shadow symbol — the
//              R1/R2 bug. Device-side reference yields the real address.)
// ---------------------------------------------------------------------------
template<int N, bool QKV, bool A_FROM_GY>
__global__ __launch_bounds__(256) void gemm_kernel(
    const float* __restrict__ Ain, const float* __restrict__ W,
    const float* __restrict__ bias, float* __restrict__ out)
{
    const float* __restrict__ A = A_FROM_GY ? (const float*)g_y : Ain;
    const int K = D_;
    __shared__ float As[16][132];   // As[k][m], transposed on store
    __shared__ float Bs[16][132];   // Bs[k][n]

    const int bm = blockIdx.y * 128;
    const int bn = blockIdx.x * 128;
    const int tid = threadIdx.x;
    const int tx = tid & 15;        // n-dim
    const int ty = tid >> 4;        // m-dim

    float acc[8][8];
    #pragma unroll
    for (int i = 0; i < 8; i++)
        #pragma unroll
        for (int j = 0; j < 8; j++) acc[i][j] = 0.f;

    for (int k0 = 0; k0 < K; k0 += 16) {
        // A tile: 128 rows x 16 cols, float4 loads, transpose into As
        #pragma unroll
        for (int it = 0; it < 2; it++) {
            int f = tid + it * 256;          // float4 index 0..511
            int row = f >> 2;                // 0..127
            int c4  = f & 3;                 // 0..3
            float4 v = *reinterpret_cast<const float4*>(
                A + (size_t)(bm + row) * K + k0 + c4 * 4);
            As[c4*4+0][row] = v.x;
            As[c4*4+1][row] = v.y;
            As[c4*4+2][row] = v.z;
            As[c4*4+3][row] = v.w;
        }
        // B tile: 16 rows x 128 cols, float4 straight
        #pragma unroll
        for (int it = 0; it < 2; it++) {
            int f = tid + it * 256;
            int row = f >> 5;                // 0..15
            int c4  = f & 31;                // 0..31
            float4 v = *reinterpret_cast<const float4*>(
                W + (size_t)(k0 + row) * N + bn + c4 * 4);
            *reinterpret_cast<float4*>(&Bs[row][c4*4]) = v;
        }
        __syncthreads();

        #pragma unroll
        for (int kk = 0; kk < 16; kk++) {
            float a[8], b[8];
            *reinterpret_cast<float4*>(&a[0]) = *reinterpret_cast<const float4*>(&As[kk][ty*8]);
            *reinterpret_cast<float4*>(&a[4]) = *reinterpret_cast<const float4*>(&As[kk][ty*8+4]);
            *reinterpret_cast<float4*>(&b[0]) = *reinterpret_cast<const float4*>(&Bs[kk][tx*8]);
            *reinterpret_cast<float4*>(&b[4]) = *reinterpret_cast<const float4*>(&Bs[kk][tx*8+4]);
            #pragma unroll
            for (int i = 0; i < 8; i++)
                #pragma unroll
                for (int j = 0; j < 8; j++)
                    acc[i][j] += a[i] * b[j];
        }
        __syncthreads();
    }

    // Epilogue
    #pragma unroll
    for (int i = 0; i < 8; i++) {
        int m = bm + ty * 8 + i;
        #pragma unroll
        for (int j = 0; j < 8; j++) {
            int n = bn + tx * 8 + j;
            float val = acc[i][j] + bias[n];
            if (QKV) {
                int which = n >> 10;         // 0=q, 1=k, 2=v
                int d = n & 1023;
                int h = d >> 6, hd = d & 63;
                int b = m >> 11, s = m & 2047;
                size_t idx = (((size_t)(b * H_ + h) * S_) + s) * HD_ + hd;
                float* dst = (which == 0) ? g_q : (which == 1) ? g_k : g_v;
                dst[idx] = val;
            } else {
                out[(size_t)m * N + n] = val;
            }
        }
    }
}

// ---------------------------------------------------------------------------
// Flash-style causal attention, fp32. One CTA = one (b,h) x 64-query tile.
// 128 threads: tx = tid&7 (k-dim, 8 cols each), ty = tid>>3 (4 rows each).
// smem rows padded to 65 floats -> all access patterns <=2-way conflicted.
// ---------------------------------------------------------------------------
#define ROWP 65
#define SMEM_ATTN (4 * 64 * ROWP * (int)sizeof(float))

__global__ __launch_bounds__(128) void attn_kernel()
{
    const int qt = blockIdx.x;                // 0..31
    const int bh = blockIdx.y;                // 0..63
    const int b  = bh >> 4;
    const int h  = bh & 15;
    const size_t head_off = (size_t)bh * S_ * HD_;
    const float* __restrict__ Qg = g_q + head_off;
    const float* __restrict__ Kg = g_k + head_off;
    const float* __restrict__ Vg = g_v + head_off;

    const int tid = threadIdx.x;
    const int tx = tid & 7;
    const int ty = tid >> 3;

    extern __shared__ float smem[];
    float* Qs = smem;                 // [64][ROWP]
    float* Ks = Qs + 64 * ROWP;
    float* Vs = Ks + 64 * ROWP;
    float* Ps = Vs + 64 * ROWP;

    // Load Q tile (rows qt*64..+63)
    #pragma unroll
    for (int it = 0; it < 8; it++) {
        int f = tid + it * 128;       // float4 index 0..1023
        int r = f >> 4, c4 = f & 15;
        float4 v = *reinterpret_cast<const float4*>(Qg + (size_t)(qt*64 + r) * HD_ + c4*4);
        Qs[r*ROWP + c4*4 + 0] = v.x;
        Qs[r*ROWP + c4*4 + 1] = v.y;
        Qs[r*ROWP + c4*4 + 2] = v.z;
        Qs[r*ROWP + c4*4 + 3] = v.w;
    }

    float o[4][8];
    float m[4], l[4];
    #pragma unroll
    for (int i = 0; i < 4; i++) {
        m[i] = -1e30f; l[i] = 0.f;
        #pragma unroll
        for (int j = 0; j < 8; j++) o[i][j] = 0.f;
    }

    const float scale = 0.125f;       // 1/sqrt(64)

    for (int kt = 0; kt <= qt; kt++) {
        __syncthreads();              // protect Ks/Vs/Ps from previous iter readers
        // Load K and V tiles
        #pragma unroll
        for (int it = 0; it < 8; it++) {
            int f = tid + it * 128;
            int r = f >> 4, c4 = f & 15;
            float4 kv = *reinterpret_cast<const float4*>(Kg + (size_t)(kt*64 + r) * HD_ + c4*4);
            Ks[r*ROWP + c4*4 + 0] = kv.x;
            Ks[r*ROWP + c4*4 + 1] = kv.y;
            Ks[r*ROWP + c4*4 + 2] = kv.z;
            Ks[r*ROWP + c4*4 + 3] = kv.w;
            float4 vv = *reinterpret_cast<const float4*>(Vg + (size_t)(kt*64 + r) * HD_ + c4*4);
            Vs[r*ROWP + c4*4 + 0] = vv.x;
            Vs[r*ROWP + c4*4 + 1] = vv.y;
            Vs[r*ROWP + c4*4 + 2] = vv.z;
            Vs[r*ROWP + c4*4 + 3] = vv.w;
        }
        __syncthreads();

        // S = Q K^T for this thread's 4x8 block
        float s[4][8];
        #pragma unroll
        for (int i = 0; i < 4; i++)
            #pragma unroll
            for (int j = 0; j < 8; j++) s[i][j] = 0.f;

        #pragma unroll 4
        for (int d = 0; d < 64; d++) {
            float qv[4], kv[8];
            #pragma unroll
            for (int i = 0; i < 4; i++) qv[i] = Qs[(ty*4 + i)*ROWP + d];
            #pragma unroll
            for (int j = 0; j < 8; j++) kv[j] = Ks[(tx*8 + j)*ROWP + d];
            #pragma unroll
            for (int i = 0; i < 4; i++)
                #pragma unroll
                for (int j = 0; j < 8; j++) s[i][j] += qv[i] * kv[j];
        }

        // scale + causal mask (only diagonal tile needs masking)
        #pragma unroll
        for (int i = 0; i < 4; i++)
            #pragma unroll
            for (int j = 0; j < 8; j++) {
                s[i][j] *= scale;
                if (kt == qt && (tx*8 + j) > (ty*4 + i)) s[i][j] = -1e30f;
            }

        // online softmax update
        #pragma unroll
        for (int i = 0; i < 4; i++) {
            float mx = s[i][0];
            #pragma unroll
            for (int j = 1; j < 8; j++) mx = fmaxf(mx, s[i][j]);
            mx = fmaxf(mx, __shfl_xor_sync(0xffffffffu, mx, 1));
            mx = fmaxf(mx, __shfl_xor_sync(0xffffffffu, mx, 2));
            mx = fmaxf(mx, __shfl_xor_sync(0xffffffffu, mx, 4));
            float m_new = fmaxf(m[i], mx);
            float alpha = __expf(m[i] - m_new);
            float rowsum = 0.f;
            #pragma unroll
            for (int j = 0; j < 8; j++) {
                float p = __expf(s[i][j] - m_new);
                s[i][j] = p;
                rowsum += p;
            }
            rowsum += __shfl_xor_sync(0xffffffffu, rowsum, 1);
            rowsum += __shfl_xor_sync(0xffffffffu, rowsum, 2);
            rowsum += __shfl_xor_sync(0xffffffffu, rowsum, 4);
            l[i] = l[i] * alpha + rowsum;
            m[i] = m_new;
            #pragma unroll
            for (int j = 0; j < 8; j++) o[i][j] *= alpha;
            // stage probabilities for the PV gemm
            #pragma unroll
            for (int j = 0; j < 8; j++)
                Ps[(ty*4 + i)*ROWP + tx*8 + j] = s[i][j];
        }
        __syncthreads();

        // O += P @ V  (thread owns rows ty*4.., HD cols tx*8..)
        #pragma unroll 4
        for (int k = 0; k < 64; k++) {
            float pv[4], vv[8];
            #pragma unroll
            for (int i = 0; i < 4; i++) pv[i] = Ps[(ty*4 + i)*ROWP + k];
            #pragma unroll
            for (int j = 0; j < 8; j++) vv[j] = Vs[k*ROWP + tx*8 + j];
            #pragma unroll
            for (int i = 0; i < 4; i++)
                #pragma unroll
                for (int j = 0; j < 8; j++)
                    o[i][j] += pv[i] * vv[j];
        }
    }

    // finalize: divide by l, write into y [B,S,D] with D-index = h*64 + col
    #pragma unroll
    for (int i = 0; i < 4; i++) {
        float inv_l = 1.0f / l[i];
        int srow = qt*64 + ty*4 + i;
        size_t base = ((size_t)b * S_ + srow) * D_ + h * HD_ + tx * 8;
        #pragma unroll
        for (int j = 0; j < 8; j++)
            g_y[base + j] = o[i][j] * inv_l;
    }
}

// ---------------------------------------------------------------------------
// Inputs bound BY ELEMENT COUNT (all five sizes pairwise distinct).
// ---------------------------------------------------------------------------
extern "C" void kernel_launch(void* const* d_in, const int* in_sizes, int n_in,
                              void* d_out, int out_size)
{
    const float* x      = nullptr;
    const float* W_attn = nullptr;
    const float* b_attn = nullptr;
    const float* W_proj = nullptr;
    const float* b_proj = nullptr;

    for (int i = 0; i < n_in; i++) {
        switch (in_sizes[i]) {
            case B_*S_*D_:    x      = (const float*)d_in[i]; break; // 8388608
            case D_*3*D_:     W_attn = (const float*)d_in[i]; break; // 3145728
            case 3*D_:        b_attn = (const float*)d_in[i]; break; // 3072
            case D_*D_:       W_proj = (const float*)d_in[i]; break; // 1048576
            case D_:          b_proj = (const float*)d_in[i]; break; // 1024
            default: break;
        }
    }
    float* out = (float*)d_out;

    cudaFuncSetAttribute(attn_kernel,
                         cudaFuncAttributeMaxDynamicSharedMemorySize, SMEM_ATTN);

    dim3 g1(N_QKV / 128, M_ / 128);   // 24 x 64
    gemm_kernel<N_QKV, true, false><<<g1, 256>>>(x, W_attn, b_attn, nullptr);

    dim3 g2(S_ / 64, B_ * H_);        // 32 x 64
    attn_kernel<<<g2, 128, SMEM_ATTN>>>();

    // A comes from g_y via device-side symbol reference (A_FROM_GY=true).
    dim3 g3(D_ / 128, M_ / 128);      // 8 x 64
    gemm_kernel<D_, false, true><<<g3, 256>>>(nullptr, W_proj, b_proj, out);
}

// round 6
// speedup vs baseline: 1.5177x; 1.5177x over previous
#include <cuda_runtime.h>
#include <cuda_bf16.h>
#include <math.h>
#include <stdint.h>

#define B_ 4
#define S_ 2048
#define D_ 1024
#define H_ 16
#define HD_ 64
#define M_ (B_*S_)      // 8192
#define N_QKV 3072

// Scratch (device globals: allocation-free per harness rules)
__device__ float g_q[B_*H_*S_*HD_];
__device__ float g_k[B_*H_*S_*HD_];
__device__ float g_v[B_*H_*S_*HD_];
__device__ float g_y[B_*S_*D_];

// Single extern-shared symbol for the whole TU (typed views per kernel).
extern __shared__ char smem_raw[];

// ---------------------------------------------------------------------------
// bf16 helpers
// ---------------------------------------------------------------------------
__device__ __forceinline__ void split_bf(float v, __nv_bfloat16& h, __nv_bfloat16& l) {
    h = __float2bfloat16_rn(v);
    l = __float2bfloat16_rn(v - __bfloat162float(h));
}

// mma.sync m16n8k16 row.col bf16 -> f32 accum (plain sm_80+ PTX; no 'a' arch gate)
__device__ __forceinline__ void mma16816(float* c, const uint32_t* a, const uint32_t* b) {
    asm volatile(
        "mma.sync.aligned.m16n8k16.row.col.f32.bf16.bf16.f32 "
        "{%0,%1,%2,%3}, {%4,%5,%6,%7}, {%8,%9}, {%0,%1,%2,%3};"
        : "+f"(c[0]), "+f"(c[1]), "+f"(c[2]), "+f"(c[3])
        : "r"(a[0]), "r"(a[1]), "r"(a[2]), "r"(a[3]), "r"(b[0]), "r"(b[1]));
}

// ===========================================================================
// HMMA bf16x3 GEMM: C[M x N_TOTAL] = A[M x 1024] @ W[1024 x N_TOTAL] + bias
// CTA 128x128, 8 warps (2m x 4n), warp tile 64x32 (4x4 m16n8k16 frags),
// K-chunk 64. smem: bf16 hi/lo planes, row stride 72 (bank-shift 4).
//   A planes: [m=128][k..] row-major;  B planes: [n=128][k..] (W^T view).
// ===========================================================================
#define LDK 72
#define PLANE (128 * LDK)                       // bf16 elements per plane
#define SMEM_GEMM (4 * PLANE * 2)               // 73728 bytes
#define KC_G 64
#define NCH_G (D_ / KC_G)                       // 16

template<int N_TOTAL, bool QKV, bool A_FROM_GY>
__global__ __launch_bounds__(256, 2)
void gemm_mma(const float* __restrict__ Ain, const float* __restrict__ W,
              const float* __restrict__ bias, float* __restrict__ out)
{
    __nv_bfloat16* sAhi = reinterpret_cast<__nv_bfloat16*>(smem_raw);
    __nv_bfloat16* sAlo = sAhi + PLANE;
    __nv_bfloat16* sBhi = sAlo + PLANE;
    __nv_bfloat16* sBlo = sBhi + PLANE;
    uint32_t* sAhi32 = reinterpret_cast<uint32_t*>(sAhi);
    uint32_t* sAlo32 = reinterpret_cast<uint32_t*>(sAlo);
    uint32_t* sBhi32 = reinterpret_cast<uint32_t*>(sBhi);
    uint32_t* sBlo32 = reinterpret_cast<uint32_t*>(sBlo);

    const float* __restrict__ A = A_FROM_GY ? (const float*)g_y : Ain;
    const int tid = threadIdx.x;
    const int wid = tid >> 5;
    const int lane = tid & 31;
    const int grp = lane >> 2;          // 0..7
    const int tig = lane & 3;           // 0..3
    const int wm = (wid >> 2) * 64;     // warp m offset in tile
    const int wn = (wid & 3) * 32;      // warp n offset in tile

    const int bm = blockIdx.y * 128;
    const int bn = blockIdx.x * 128;

    float acc[4][4][4];
    #pragma unroll
    for (int i = 0; i < 4; i++)
        #pragma unroll
        for (int j = 0; j < 4; j++)
            #pragma unroll
            for (int q = 0; q < 4; q++) acc[i][j][q] = 0.f;

    const float* Abase = A + (size_t)bm * D_;
    // B loader: thread owns column n = tid&127, k-half = tid>>7
    const int nl = tid & 127;
    const int kh = (tid >> 7) * 32;

    for (int c = 0; c < NCH_G; c++) {
        __syncthreads();   // previous chunk's MMA reads done before overwrite

        // ---- A tile: 128 x 64 fp32 -> hi/lo bf16 ----
        const float* Ab = Abase + c * KC_G;
        #pragma unroll
        for (int i = 0; i < 8; i++) {
            int f = tid + i * 256;          // float4 idx 0..2047
            int row = f >> 4;               // 0..127
            int c4  = f & 15;               // 0..15
            float4 v = *reinterpret_cast<const float4*>(Ab + (size_t)row * D_ + c4 * 4);
            __nv_bfloat16 h0,h1,h2,h3,l0,l1,l2,l3;
            split_bf(v.x,h0,l0); split_bf(v.y,h1,l1);
            split_bf(v.z,h2,l2); split_bf(v.w,h3,l3);
            int o = row * LDK + c4 * 4;
            sAhi[o+0]=h0; sAhi[o+1]=h1; sAhi[o+2]=h2; sAhi[o+3]=h3;
            sAlo[o+0]=l0; sAlo[o+1]=l1; sAlo[o+2]=l2; sAlo[o+3]=l3;
        }

        // ---- B tile: W[k][n] -> sB[n][k], 128 n x 64 k ----
        const float* Wb = W + (size_t)(c * KC_G + kh) * N_TOTAL + bn + nl;
        #pragma unroll 8
        for (int kk = 0; kk < 32; kk++) {
            float v = Wb[(size_t)kk * N_TOTAL];
            __nv_bfloat16 h, l;
            split_bf(v, h, l);
            int o = nl * LDK + kh + kk;
            sBhi[o] = h; sBlo[o] = l;
        }

        __syncthreads();

        // ---- MMA: 4 k16-steps ----
        #pragma unroll
        for (int ks = 0; ks < 4; ks++) {
            const int k0 = ks * 16;
            // B fragments: 4 n-tiles x {hi,lo}
            uint32_t bh[4][2], bl[4][2];
            #pragma unroll
            for (int nt = 0; nt < 4; nt++) {
                int n0 = wn + nt * 8;
                int ob = ((n0 + grp) * LDK + k0 + 2 * tig) >> 1;   // uint32 index
                bh[nt][0] = sBhi32[ob];       bl[nt][0] = sBlo32[ob];
                bh[nt][1] = sBhi32[ob + 4];   bl[nt][1] = sBlo32[ob + 4];
            }
            #pragma unroll
            for (int mt = 0; mt < 4; mt++) {
                int m0 = wm + mt * 16;
                int oa  = ((m0 + grp) * LDK + k0 + 2 * tig) >> 1;
                int oa8 = oa + (8 * LDK >> 1);
                uint32_t ah[4], al[4];
                ah[0] = sAhi32[oa];      ah[1] = sAhi32[oa8];
                ah[2] = sAhi32[oa + 4];  ah[3] = sAhi32[oa8 + 4];
                al[0] = sAlo32[oa];      al[1] = sAlo32[oa8];
                al[2] = sAlo32[oa + 4];  al[3] = sAlo32[oa8 + 4];
                #pragma unroll
                for (int nt = 0; nt < 4; nt++) {
                    mma16816(acc[mt][nt], ah, bh[nt]);   // hi*hi
                    mma16816(acc[mt][nt], ah, bl[nt]);   // hi*lo
                    mma16816(acc[mt][nt], al, bh[nt]);   // lo*hi
                }
            }
        }
    }

    // ---- Epilogue: c0,c1=(m=grp, n=2tig,2tig+1); c2,c3=(m=grp+8, same n) ----
    #pragma unroll
    for (int mt = 0; mt < 4; mt++) {
        #pragma unroll
        for (int half = 0; half < 2; half++) {
            int m = bm + wm + mt * 16 + grp + half * 8;
            #pragma unroll
            for (int nt = 0; nt < 4; nt++) {
                int n = bn + wn + nt * 8 + 2 * tig;    // even
                float v0 = acc[mt][nt][half*2 + 0] + bias[n];
                float v1 = acc[mt][nt][half*2 + 1] + bias[n + 1];
                if (QKV) {
                    int which = n >> 10;
                    int d0 = n & 1023;
                    int h = d0 >> 6, hd = d0 & 63;
                    int b = m >> 11, s = m & 2047;
                    float* dst = (which == 0) ? g_q : (which == 1) ? g_k : g_v;
                    size_t idx = (((size_t)(b * H_ + h) * S_) + s) * HD_ + hd;
                    *reinterpret_cast<float2*>(dst + idx) = make_float2(v0, v1);
                } else {
                    *reinterpret_cast<float2*>(out + (size_t)m * N_TOTAL + n) =
                        make_float2(v0, v1);
                }
            }
        }
    }
}

// ---------------------------------------------------------------------------
// Flash-style causal attention, fp32 (same math as R3 passing kernel).
// ---------------------------------------------------------------------------
#define ROWP 65
#define SMEM_ATTN (4 * 64 * ROWP * (int)sizeof(float))

__global__ __launch_bounds__(128) void attn_kernel()
{
    const int qt = blockIdx.x;
    const int bh = blockIdx.y;
    const int b  = bh >> 4;
    const int h  = bh & 15;
    const size_t head_off = (size_t)bh * S_ * HD_;
    const float* __restrict__ Qg = g_q + head_off;
    const float* __restrict__ Kg = g_k + head_off;
    const float* __restrict__ Vg = g_v + head_off;

    const int tid = threadIdx.x;
    const int tx = tid & 7;
    const int ty = tid >> 3;

    float* smem = reinterpret_cast<float*>(smem_raw);
    float* Qs = smem;
    float* Ks = Qs + 64 * ROWP;
    float* Vs = Ks + 64 * ROWP;
    float* Ps = Vs + 64 * ROWP;

    #pragma unroll
    for (int it = 0; it < 8; it++) {
        int f = tid + it * 128;
        int r = f >> 4, c4 = f & 15;
        float4 v = *reinterpret_cast<const float4*>(Qg + (size_t)(qt*64 + r) * HD_ + c4*4);
        Qs[r*ROWP + c4*4 + 0] = v.x;
        Qs[r*ROWP + c4*4 + 1] = v.y;
        Qs[r*ROWP + c4*4 + 2] = v.z;
        Qs[r*ROWP + c4*4 + 3] = v.w;
    }

    float o[4][8];
    float m[4], l[4];
    #pragma unroll
    for (int i = 0; i < 4; i++) {
        m[i] = -1e30f; l[i] = 0.f;
        #pragma unroll
        for (int j = 0; j < 8; j++) o[i][j] = 0.f;
    }

    const float scale = 0.125f;

    for (int kt = 0; kt <= qt; kt++) {
        __syncthreads();
        #pragma unroll
        for (int it = 0; it < 8; it++) {
            int f = tid + it * 128;
            int r = f >> 4, c4 = f & 15;
            float4 kv = *reinterpret_cast<const float4*>(Kg + (size_t)(kt*64 + r) * HD_ + c4*4);
            Ks[r*ROWP + c4*4 + 0] = kv.x;
            Ks[r*ROWP + c4*4 + 1] = kv.y;
            Ks[r*ROWP + c4*4 + 2] = kv.z;
            Ks[r*ROWP + c4*4 + 3] = kv.w;
            float4 vv = *reinterpret_cast<const float4*>(Vg + (size_t)(kt*64 + r) * HD_ + c4*4);
            Vs[r*ROWP + c4*4 + 0] = vv.x;
            Vs[r*ROWP + c4*4 + 1] = vv.y;
            Vs[r*ROWP + c4*4 + 2] = vv.z;
            Vs[r*ROWP + c4*4 + 3] = vv.w;
        }
        __syncthreads();

        float s[4][8];
        #pragma unroll
        for (int i = 0; i < 4; i++)
            #pragma unroll
            for (int j = 0; j < 8; j++) s[i][j] = 0.f;

        #pragma unroll 4
        for (int d = 0; d < 64; d++) {
            float qv[4], kv[8];
            #pragma unroll
            for (int i = 0; i < 4; i++) qv[i] = Qs[(ty*4 + i)*ROWP + d];
            #pragma unroll
            for (int j = 0; j < 8; j++) kv[j] = Ks[(tx*8 + j)*ROWP + d];
            #pragma unroll
            for (int i = 0; i < 4; i++)
                #pragma unroll
                for (int j = 0; j < 8; j++) s[i][j] += qv[i] * kv[j];
        }

        #pragma unroll
        for (int i = 0; i < 4; i++)
            #pragma unroll
            for (int j = 0; j < 8; j++) {
                s[i][j] *= scale;
                if (kt == qt && (tx*8 + j) > (ty*4 + i)) s[i][j] = -1e30f;
            }

        #pragma unroll
        for (int i = 0; i < 4; i++) {
            float mx = s[i][0];
            #pragma unroll
            for (int j = 1; j < 8; j++) mx = fmaxf(mx, s[i][j]);
            mx = fmaxf(mx, __shfl_xor_sync(0xffffffffu, mx, 1));
            mx = fmaxf(mx, __shfl_xor_sync(0xffffffffu, mx, 2));
            mx = fmaxf(mx, __shfl_xor_sync(0xffffffffu, mx, 4));
            float m_new = fmaxf(m[i], mx);
            float alpha = __expf(m[i] - m_new);
            float rowsum = 0.f;
            #pragma unroll
            for (int j = 0; j < 8; j++) {
                float p = __expf(s[i][j] - m_new);
                s[i][j] = p;
                rowsum += p;
            }
            rowsum += __shfl_xor_sync(0xffffffffu, rowsum, 1);
            rowsum += __shfl_xor_sync(0xffffffffu, rowsum, 2);
            rowsum += __shfl_xor_sync(0xffffffffu, rowsum, 4);
            l[i] = l[i] * alpha + rowsum;
            m[i] = m_new;
            #pragma unroll
            for (int j = 0; j < 8; j++) o[i][j] *= alpha;
            #pragma unroll
            for (int j = 0; j < 8; j++)
                Ps[(ty*4 + i)*ROWP + tx*8 + j] = s[i][j];
        }
        __syncthreads();

        #pragma unroll 4
        for (int k = 0; k < 64; k++) {
            float pv[4], vv[8];
            #pragma unroll
            for (int i = 0; i < 4; i++) pv[i] = Ps[(ty*4 + i)*ROWP + k];
            #pragma unroll
            for (int j = 0; j < 8; j++) vv[j] = Vs[k*ROWP + tx*8 + j];
            #pragma unroll
            for (int i = 0; i < 4; i++)
                #pragma unroll
                for (int j = 0; j < 8; j++)
                    o[i][j] += pv[i] * vv[j];
        }
    }

    #pragma unroll
    for (int i = 0; i < 4; i++) {
        float inv_l = 1.0f / l[i];
        int srow = qt*64 + ty*4 + i;
        size_t base = ((size_t)b * S_ + srow) * D_ + h * HD_ + tx * 8;
        #pragma unroll
        for (int j = 0; j < 8; j++)
            g_y[base + j] = o[i][j] * inv_l;
    }
}

// ---------------------------------------------------------------------------
// Inputs bound BY ELEMENT COUNT (all five sizes pairwise distinct).
// ---------------------------------------------------------------------------
extern "C" void kernel_launch(void* const* d_in, const int* in_sizes, int n_in,
                              void* d_out, int out_size)
{
    const float* x      = nullptr;
    const float* W_attn = nullptr;
    const float* b_attn = nullptr;
    const float* W_proj = nullptr;
    const float* b_proj = nullptr;

    for (int i = 0; i < n_in; i++) {
        switch (in_sizes[i]) {
            case B_*S_*D_:    x      = (const float*)d_in[i]; break; // 8388608
            case D_*3*D_:     W_attn = (const float*)d_in[i]; break; // 3145728
            case 3*D_:        b_attn = (const float*)d_in[i]; break; // 3072
            case D_*D_:       W_proj = (const float*)d_in[i]; break; // 1048576
            case D_:          b_proj = (const float*)d_in[i]; break; // 1024
            default: break;
        }
    }
    float* out = (float*)d_out;

    cudaFuncSetAttribute(gemm_mma<N_QKV, true, false>,
                         cudaFuncAttributeMaxDynamicSharedMemorySize, SMEM_GEMM);
    cudaFuncSetAttribute(gemm_mma<D_, false, true>,
                         cudaFuncAttributeMaxDynamicSharedMemorySize, SMEM_GEMM);
    cudaFuncSetAttribute(attn_kernel,
                         cudaFuncAttributeMaxDynamicSharedMemorySize, SMEM_ATTN);

    dim3 g1(N_QKV / 128, M_ / 128);   // 24 x 64
    gemm_mma<N_QKV, true, false><<<g1, 256, SMEM_GEMM>>>(x, W_attn, b_attn, nullptr);

    dim3 g2(S_ / 64, B_ * H_);        // 32 x 64
    attn_kernel<<<g2, 128, SMEM_ATTN>>>();

    dim3 g3(D_ / 128, M_ / 128);      // 8 x 64
    gemm_mma<D_, false, true><<<g3, 256, SMEM_GEMM>>>(nullptr, W_proj, b_proj, out);
}

// round 7
// speedup vs baseline: 2.7300x; 1.7987x over previous
#include <cuda_runtime.h>
#include <cuda_bf16.h>
#include <math.h>
#include <stdint.h>

#define B_ 4
#define S_ 2048
#define D_ 1024
#define H_ 16
#define HD_ 64
#define M_ (B_*S_)      // 8192
#define N_QKV 3072

// Scratch (device globals: allocation-free per harness rules)
__device__ float g_q[B_*H_*S_*HD_];
__device__ float g_k[B_*H_*S_*HD_];
__device__ float g_v[B_*H_*S_*HD_];
__device__ float g_y[B_*S_*D_];

// Single extern-shared symbol for the whole TU (typed views per kernel).
extern __shared__ char smem_raw[];

// ---------------------------------------------------------------------------
// bf16 helpers
// ---------------------------------------------------------------------------
__device__ __forceinline__ void split_bf(float v, __nv_bfloat16& h, __nv_bfloat16& l) {
    h = __float2bfloat16_rn(v);
    l = __float2bfloat16_rn(v - __bfloat162float(h));
}
__device__ __forceinline__ uint32_t pk2f(float a, float b) {
    __nv_bfloat162 t(__float2bfloat16_rn(a), __float2bfloat16_rn(b));
    return *reinterpret_cast<uint32_t*>(&t);
}

// mma.sync m16n8k16 row.col bf16 -> f32 accum (plain sm_80+ PTX)
__device__ __forceinline__ void mma16816(float* c, const uint32_t* a, const uint32_t* b) {
    asm volatile(
        "mma.sync.aligned.m16n8k16.row.col.f32.bf16.bf16.f32 "
        "{%0,%1,%2,%3}, {%4,%5,%6,%7}, {%8,%9}, {%0,%1,%2,%3};"
        : "+f"(c[0]), "+f"(c[1]), "+f"(c[2]), "+f"(c[3])
        : "r"(a[0]), "r"(a[1]), "r"(a[2]), "r"(a[3]), "r"(b[0]), "r"(b[1]));
}

// ===========================================================================
// HMMA bf16x3 GEMM (unchanged from passing R6 kernel).
// ===========================================================================
#define LDK 72
#define PLANE (128 * LDK)
#define SMEM_GEMM (4 * PLANE * 2)               // 73728 bytes
#define KC_G 64
#define NCH_G (D_ / KC_G)                       // 16

template<int N_TOTAL, bool QKV, bool A_FROM_GY>
__global__ __launch_bounds__(256, 2)
void gemm_mma(const float* __restrict__ Ain, const float* __restrict__ W,
              const float* __restrict__ bias, float* __restrict__ out)
{
    __nv_bfloat16* sAhi = reinterpret_cast<__nv_bfloat16*>(smem_raw);
    __nv_bfloat16* sAlo = sAhi + PLANE;
    __nv_bfloat16* sBhi = sAlo + PLANE;
    __nv_bfloat16* sBlo = sBhi + PLANE;
    uint32_t* sAhi32 = reinterpret_cast<uint32_t*>(sAhi);
    uint32_t* sAlo32 = reinterpret_cast<uint32_t*>(sAlo);
    uint32_t* sBhi32 = reinterpret_cast<uint32_t*>(sBhi);
    uint32_t* sBlo32 = reinterpret_cast<uint32_t*>(sBlo);

    const float* __restrict__ A = A_FROM_GY ? (const float*)g_y : Ain;
    const int tid = threadIdx.x;
    const int wid = tid >> 5;
    const int lane = tid & 31;
    const int grp = lane >> 2;
    const int tig = lane & 3;
    const int wm = (wid >> 2) * 64;
    const int wn = (wid & 3) * 32;

    const int bm = blockIdx.y * 128;
    const int bn = blockIdx.x * 128;

    float acc[4][4][4];
    #pragma unroll
    for (int i = 0; i < 4; i++)
        #pragma unroll
        for (int j = 0; j < 4; j++)
            #pragma unroll
            for (int q = 0; q < 4; q++) acc[i][j][q] = 0.f;

    const float* Abase = A + (size_t)bm * D_;
    const int nl = tid & 127;
    const int kh = (tid >> 7) * 32;

    for (int c = 0; c < NCH_G; c++) {
        __syncthreads();

        const float* Ab = Abase + c * KC_G;
        #pragma unroll
        for (int i = 0; i < 8; i++) {
            int f = tid + i * 256;
            int row = f >> 4;
            int c4  = f & 15;
            float4 v = *reinterpret_cast<const float4*>(Ab + (size_t)row * D_ + c4 * 4);
            __nv_bfloat16 h0,h1,h2,h3,l0,l1,l2,l3;
            split_bf(v.x,h0,l0); split_bf(v.y,h1,l1);
            split_bf(v.z,h2,l2); split_bf(v.w,h3,l3);
            int o = row * LDK + c4 * 4;
            sAhi[o+0]=h0; sAhi[o+1]=h1; sAhi[o+2]=h2; sAhi[o+3]=h3;
            sAlo[o+0]=l0; sAlo[o+1]=l1; sAlo[o+2]=l2; sAlo[o+3]=l3;
        }

        const float* Wb = W + (size_t)(c * KC_G + kh) * N_TOTAL + bn + nl;
        #pragma unroll 8
        for (int kk = 0; kk < 32; kk++) {
            float v = Wb[(size_t)kk * N_TOTAL];
            __nv_bfloat16 h, l;
            split_bf(v, h, l);
            int o = nl * LDK + kh + kk;
            sBhi[o] = h; sBlo[o] = l;
        }

        __syncthreads();

        #pragma unroll
        for (int ks = 0; ks < 4; ks++) {
            const int k0 = ks * 16;
            uint32_t bh[4][2], bl[4][2];
            #pragma unroll
            for (int nt = 0; nt < 4; nt++) {
                int n0 = wn + nt * 8;
                int ob = ((n0 + grp) * LDK + k0 + 2 * tig) >> 1;
                bh[nt][0] = sBhi32[ob];       bl[nt][0] = sBlo32[ob];
                bh[nt][1] = sBhi32[ob + 4];   bl[nt][1] = sBlo32[ob + 4];
            }
            #pragma unroll
            for (int mt = 0; mt < 4; mt++) {
                int m0 = wm + mt * 16;
                int oa  = ((m0 + grp) * LDK + k0 + 2 * tig) >> 1;
                int oa8 = oa + (8 * LDK >> 1);
                uint32_t ah[4], al[4];
                ah[0] = sAhi32[oa];      ah[1] = sAhi32[oa8];
                ah[2] = sAhi32[oa + 4];  ah[3] = sAhi32[oa8 + 4];
                al[0] = sAlo32[oa];      al[1] = sAlo32[oa8];
                al[2] = sAlo32[oa + 4];  al[3] = sAlo32[oa8 + 4];
                #pragma unroll
                for (int nt = 0; nt < 4; nt++) {
                    mma16816(acc[mt][nt], ah, bh[nt]);
                    mma16816(acc[mt][nt], ah, bl[nt]);
                    mma16816(acc[mt][nt], al, bh[nt]);
                }
            }
        }
    }

    #pragma unroll
    for (int mt = 0; mt < 4; mt++) {
        #pragma unroll
        for (int half = 0; half < 2; half++) {
            int m = bm + wm + mt * 16 + grp + half * 8;
            #pragma unroll
            for (int nt = 0; nt < 4; nt++) {
                int n = bn + wn + nt * 8 + 2 * tig;
                float v0 = acc[mt][nt][half*2 + 0] + bias[n];
                float v1 = acc[mt][nt][half*2 + 1] + bias[n + 1];
                if (QKV) {
                    int which = n >> 10;
                    int d0 = n & 1023;
                    int h = d0 >> 6, hd = d0 & 63;
                    int b = m >> 11, s = m & 2047;
                    float* dst = (which == 0) ? g_q : (which == 1) ? g_k : g_v;
                    size_t idx = (((size_t)(b * H_ + h) * S_) + s) * HD_ + hd;
                    *reinterpret_cast<float2*>(dst + idx) = make_float2(v0, v1);
                } else {
                    *reinterpret_cast<float2*>(out + (size_t)m * N_TOTAL + n) =
                        make_float2(v0, v1);
                }
            }
        }
    }
}

// ===========================================================================
// Flash attention on mma.sync bf16x3. One CTA = (b,h) x 64-q tile, 4 warps
// x 16 rows. S-fragments feed P@V directly (C-layout == A-layout); V staged
// transposed. Online softmax on fragment rows (grp, grp+8) via tig-shuffles.
// ===========================================================================
#define AROW 72                       // Q/K smem stride (bf16)
#define VROW 66                       // V smem stride (bf16), even
#define SQK (64 * AROW)               // 4608 elems per plane
#define SV  (64 * VROW)               // 4224 elems per plane
#define SMEM_ATTN ((2 * SQK + 2 * SV) * 2)   // 35328 bytes

__global__ __launch_bounds__(128) void attn_mma()
{
    const int qt = blockIdx.x;                // 0..31
    const int bh = blockIdx.y;                // 0..63
    const int b  = bh >> 4;
    const int h  = bh & 15;
    const size_t head = (size_t)bh * S_ * HD_;
    const float* __restrict__ Qg = g_q + head;
    const float* __restrict__ Kg = g_k + head;
    const float* __restrict__ Vg = g_v + head;

    const int tid = threadIdx.x;
    const int wid = tid >> 5;                 // 0..3
    const int lane = tid & 31;
    const int grp = lane >> 2;                // 0..7
    const int tig = lane & 3;                 // 0..3
    const int wm = wid * 16;                  // warp's row base in tile

    __nv_bfloat16* sKhi = reinterpret_cast<__nv_bfloat16*>(smem_raw);
    __nv_bfloat16* sKlo = sKhi + SQK;
    __nv_bfloat16* sVhi = sKlo + SQK;
    __nv_bfloat16* sVlo = sVhi + SV;
    uint32_t* sKhi32 = reinterpret_cast<uint32_t*>(sKhi);
    uint32_t* sKlo32 = reinterpret_cast<uint32_t*>(sKlo);
    uint32_t* sVhi32 = reinterpret_cast<uint32_t*>(sVhi);
    uint32_t* sVlo32 = reinterpret_cast<uint32_t*>(sVlo);

    // ---- Stage Q through K-plane smem, pull A-fragments to registers ----
    #pragma unroll
    for (int it = 0; it < 8; it++) {
        int f = tid + it * 128;               // float4 idx 0..1023
        int r = f >> 4, c4 = f & 15;
        float4 v = *reinterpret_cast<const float4*>(Qg + (size_t)(qt*64 + r) * HD_ + c4*4);
        __nv_bfloat16 h0,h1,h2,h3,l0,l1,l2,l3;
        split_bf(v.x,h0,l0); split_bf(v.y,h1,l1);
        split_bf(v.z,h2,l2); split_bf(v.w,h3,l3);
        int o = r * AROW + c4 * 4;
        sKhi[o+0]=h0; sKhi[o+1]=h1; sKhi[o+2]=h2; sKhi[o+3]=h3;
        sKlo[o+0]=l0; sKlo[o+1]=l1; sKlo[o+2]=l2; sKlo[o+3]=l3;
    }
    __syncthreads();
    uint32_t qh[4][4], ql[4][4];
    #pragma unroll
    for (int ks = 0; ks < 4; ks++) {
        int oa  = ((wm + grp) * AROW + ks * 16 + 2 * tig) >> 1;
        int oa8 = oa + (8 * AROW >> 1);
        qh[ks][0] = sKhi32[oa];      qh[ks][1] = sKhi32[oa8];
        qh[ks][2] = sKhi32[oa + 4];  qh[ks][3] = sKhi32[oa8 + 4];
        ql[ks][0] = sKlo32[oa];      ql[ks][1] = sKlo32[oa8];
        ql[ks][2] = sKlo32[oa + 4];  ql[ks][3] = sKlo32[oa8 + 4];
    }

    float o[8][4];
    #pragma unroll
    for (int nt = 0; nt < 8; nt++)
        #pragma unroll
        for (int q = 0; q < 4; q++) o[nt][q] = 0.f;
    float mrow[2] = {-1e30f, -1e30f};
    float lrow[2] = {0.f, 0.f};
    const float scale = 0.125f;

    for (int kt = 0; kt <= qt; kt++) {
        __syncthreads();   // previous iter's smem reads complete

        // ---- K tile: [seq][hd] hi/lo ----
        #pragma unroll
        for (int it = 0; it < 8; it++) {
            int f = tid + it * 128;
            int r = f >> 4, c4 = f & 15;
            float4 v = *reinterpret_cast<const float4*>(Kg + (size_t)(kt*64 + r) * HD_ + c4*4);
            __nv_bfloat16 h0,h1,h2,h3,l0,l1,l2,l3;
            split_bf(v.x,h0,l0); split_bf(v.y,h1,l1);
            split_bf(v.z,h2,l2); split_bf(v.w,h3,l3);
            int oo = r * AROW + c4 * 4;
            sKhi[oo+0]=h0; sKhi[oo+1]=h1; sKhi[oo+2]=h2; sKhi[oo+3]=h3;
            sKlo[oo+0]=l0; sKlo[oo+1]=l1; sKlo[oo+2]=l2; sKlo[oo+3]=l3;
        }
        // ---- V tile transposed: sV[hd][seq] hi/lo ----
        {
            int hd4 = (tid & 15) * 4;
            int sq0 = tid >> 4;               // 0..7
            #pragma unroll
            for (int it = 0; it < 8; it++) {
                int sq = sq0 + it * 8;
                float4 v = *reinterpret_cast<const float4*>(Vg + (size_t)(kt*64 + sq) * HD_ + hd4);
                __nv_bfloat16 hh, ll;
                split_bf(v.x, hh, ll); sVhi[(hd4+0)*VROW + sq] = hh; sVlo[(hd4+0)*VROW + sq] = ll;
                split_bf(v.y, hh, ll); sVhi[(hd4+1)*VROW + sq] = hh; sVlo[(hd4+1)*VROW + sq] = ll;
                split_bf(v.z, hh, ll); sVhi[(hd4+2)*VROW + sq] = hh; sVlo[(hd4+2)*VROW + sq] = ll;
                split_bf(v.w, hh, ll); sVhi[(hd4+3)*VROW + sq] = hh; sVlo[(hd4+3)*VROW + sq] = ll;
            }
        }
        __syncthreads();

        // ---- S = Q K^T (16 x 64 per warp), 3-term split ----
        float s[8][4];
        #pragma unroll
        for (int nt = 0; nt < 8; nt++)
            #pragma unroll
            for (int q = 0; q < 4; q++) s[nt][q] = 0.f;

        #pragma unroll
        for (int nt = 0; nt < 8; nt++) {
            #pragma unroll
            for (int ks = 0; ks < 4; ks++) {
                int ob = ((nt * 8 + grp) * AROW + ks * 16 + 2 * tig) >> 1;
                uint32_t bhf[2], blf[2];
                bhf[0] = sKhi32[ob]; bhf[1] = sKhi32[ob + 4];
                blf[0] = sKlo32[ob]; blf[1] = sKlo32[ob + 4];
                mma16816(s[nt], qh[ks], bhf);
                mma16816(s[nt], qh[ks], blf);
                mma16816(s[nt], ql[ks], bhf);
            }
        }

        // ---- scale + causal mask ----
        #pragma unroll
        for (int nt = 0; nt < 8; nt++) {
            #pragma unroll
            for (int q = 0; q < 4; q++) s[nt][q] *= scale;
        }
        if (kt == qt) {
            #pragma unroll
            for (int nt = 0; nt < 8; nt++) {
                int col = nt * 8 + 2 * tig;
                int r0 = wm + grp, r1 = r0 + 8;
                if (col     > r0) s[nt][0] = -1e30f;
                if (col + 1 > r0) s[nt][1] = -1e30f;
                if (col     > r1) s[nt][2] = -1e30f;
                if (col + 1 > r1) s[nt][3] = -1e30f;
            }
        }

        // ---- online softmax ----
        float mx0 = -1e30f, mx1 = -1e30f;
        #pragma unroll
        for (int nt = 0; nt < 8; nt++) {
            mx0 = fmaxf(mx0, fmaxf(s[nt][0], s[nt][1]));
            mx1 = fmaxf(mx1, fmaxf(s[nt][2], s[nt][3]));
        }
        mx0 = fmaxf(mx0, __shfl_xor_sync(0xffffffffu, mx0, 1));
        mx0 = fmaxf(mx0, __shfl_xor_sync(0xffffffffu, mx0, 2));
        mx1 = fmaxf(mx1, __shfl_xor_sync(0xffffffffu, mx1, 1));
        mx1 = fmaxf(mx1, __shfl_xor_sync(0xffffffffu, mx1, 2));
        float mn0 = fmaxf(mrow[0], mx0);
        float mn1 = fmaxf(mrow[1], mx1);
        float a0 = __expf(mrow[0] - mn0);
        float a1 = __expf(mrow[1] - mn1);
        float sum0 = 0.f, sum1 = 0.f;
        #pragma unroll
        for (int nt = 0; nt < 8; nt++) {
            s[nt][0] = __expf(s[nt][0] - mn0);
            s[nt][1] = __expf(s[nt][1] - mn0);
            s[nt][2] = __expf(s[nt][2] - mn1);
            s[nt][3] = __expf(s[nt][3] - mn1);
            sum0 += s[nt][0] + s[nt][1];
            sum1 += s[nt][2] + s[nt][3];
        }
        sum0 += __shfl_xor_sync(0xffffffffu, sum0, 1);
        sum0 += __shfl_xor_sync(0xffffffffu, sum0, 2);
        sum1 += __shfl_xor_sync(0xffffffffu, sum1, 1);
        sum1 += __shfl_xor_sync(0xffffffffu, sum1, 2);
        lrow[0] = lrow[0] * a0 + sum0;
        lrow[1] = lrow[1] * a1 + sum1;
        mrow[0] = mn0; mrow[1] = mn1;
        #pragma unroll
        for (int nt = 0; nt < 8; nt++) {
            o[nt][0] *= a0; o[nt][1] *= a0;
            o[nt][2] *= a1; o[nt][3] *= a1;
        }

        // ---- pack P fragments (C layout == A layout; k-dim = S's n-dim) ----
        uint32_t ph[4][4], pl[4][4];
        #pragma unroll
        for (int ks = 0; ks < 4; ks++) {
            const float* c0 = s[2*ks];
            const float* c1 = s[2*ks + 1];
            ph[ks][0] = pk2f(c0[0], c0[1]);
            ph[ks][1] = pk2f(c0[2], c0[3]);
            ph[ks][2] = pk2f(c1[0], c1[1]);
            ph[ks][3] = pk2f(c1[2], c1[3]);
            float r00 = c0[0] - __bfloat162float(__float2bfloat16_rn(c0[0]));
            float r01 = c0[1] - __bfloat162float(__float2bfloat16_rn(c0[1]));
            float r02 = c0[2] - __bfloat162float(__float2bfloat16_rn(c0[2]));
            float r03 = c0[3] - __bfloat162float(__float2bfloat16_rn(c0[3]));
            float r10 = c1[0] - __bfloat162float(__float2bfloat16_rn(c1[0]));
            float r11 = c1[1] - __bfloat162float(__float2bfloat16_rn(c1[1]));
            float r12 = c1[2] - __bfloat162float(__float2bfloat16_rn(c1[2]));
            float r13 = c1[3] - __bfloat162float(__float2bfloat16_rn(c1[3]));
            pl[ks][0] = pk2f(r00, r01);
            pl[ks][1] = pk2f(r02, r03);
            pl[ks][2] = pk2f(r10, r11);
            pl[ks][3] = pk2f(r12, r13);
        }

        // ---- O += P V (n = hd, k = seq), 3-term split ----
        #pragma unroll
        for (int nt = 0; nt < 8; nt++) {
            #pragma unroll
            for (int ks = 0; ks < 4; ks++) {
                int ob = (nt * 8 + grp) * (VROW/2) + ks * 8 + tig;
                uint32_t vh[2], vl[2];
                vh[0] = sVhi32[ob]; vh[1] = sVhi32[ob + 4];
                vl[0] = sVlo32[ob]; vl[1] = sVlo32[ob + 4];
                mma16816(o[nt], ph[ks], vh);
                mma16816(o[nt], ph[ks], vl);
                mma16816(o[nt], pl[ks], vh);
            }
        }
    }

    // ---- finalize + write ----
    float inv0 = 1.0f / lrow[0];
    float inv1 = 1.0f / lrow[1];
    int r0 = qt * 64 + wm + grp;
    int r1 = r0 + 8;
    #pragma unroll
    for (int nt = 0; nt < 8; nt++) {
        int col = h * HD_ + nt * 8 + 2 * tig;
        *reinterpret_cast<float2*>(g_y + ((size_t)b * S_ + r0) * D_ + col) =
            make_float2(o[nt][0] * inv0, o[nt][1] * inv0);
        *reinterpret_cast<float2*>(g_y + ((size_t)b * S_ + r1) * D_ + col) =
            make_float2(o[nt][2] * inv1, o[nt][3] * inv1);
    }
}

// ---------------------------------------------------------------------------
// Inputs bound BY ELEMENT COUNT (all five sizes pairwise distinct).
// ---------------------------------------------------------------------------
extern "C" void kernel_launch(void* const* d_in, const int* in_sizes, int n_in,
                              void* d_out, int out_size)
{
    const float* x      = nullptr;
    const float* W_attn = nullptr;
    const float* b_attn = nullptr;
    const float* W_proj = nullptr;
    const float* b_proj = nullptr;

    for (int i = 0; i < n_in; i++) {
        switch (in_sizes[i]) {
            case B_*S_*D_:    x      = (const float*)d_in[i]; break; // 8388608
            case D_*3*D_:     W_attn = (const float*)d_in[i]; break; // 3145728
            case 3*D_:        b_attn = (const float*)d_in[i]; break; // 3072
            case D_*D_:       W_proj = (const float*)d_in[i]; break; // 1048576
            case D_:          b_proj = (const float*)d_in[i]; break; // 1024
            default: break;
        }
    }
    float* out = (float*)d_out;

    cudaFuncSetAttribute(gemm_mma<N_QKV, true, false>,
                         cudaFuncAttributeMaxDynamicSharedMemorySize, SMEM_GEMM);
    cudaFuncSetAttribute(gemm_mma<D_, false, true>,
                         cudaFuncAttributeMaxDynamicSharedMemorySize, SMEM_GEMM);
    cudaFuncSetAttribute(attn_mma,
                         cudaFuncAttributeMaxDynamicSharedMemorySize, SMEM_ATTN);

    dim3 g1(N_QKV / 128, M_ / 128);   // 24 x 64
    gemm_mma<N_QKV, true, false><<<g1, 256, SMEM_GEMM>>>(x, W_attn, b_attn, nullptr);

    dim3 g2(S_ / 64, B_ * H_);        // 32 x 64
    attn_mma<<<g2, 128, SMEM_ATTN>>>();

    dim3 g3(D_ / 128, M_ / 128);      // 8 x 64
    gemm_mma<D_, false, true><<<g3, 256, SMEM_GEMM>>>(nullptr, W_proj, b_proj, out);
}

// round 8
// speedup vs baseline: 3.0552x; 1.1191x over previous
#include <cuda_runtime.h>
#include <cuda_bf16.h>
#include <stdint.h>

#define B_ 4
#define S_ 2048
#define D_ 1024
#define H_ 16
#define HD_ 64
#define M_ (B_*S_)      // 8192
#define N_QKV 3072
#define QKVN (B_*H_*S_*HD_)   // 8388608

typedef __nv_bfloat16 bf16;

// ---- Pre-split bf16 hi/lo planes (device globals; allocation-free) ----
__device__ bf16 g_xhi[M_*D_],    g_xlo[M_*D_];       // x        [M,K]
__device__ bf16 g_wahiT[N_QKV*D_], g_waloT[N_QKV*D_];// W_attn^T [N,K]
__device__ bf16 g_wphiT[D_*D_],  g_wploT[D_*D_];     // W_proj^T [N,K]
__device__ bf16 g_qhi[QKVN], g_qlo[QKVN];            // q [B,H,S,HD]
__device__ bf16 g_khi[QKVN], g_klo[QKVN];            // k [B,H,S,HD]
__device__ bf16 g_vThi[QKVN], g_vTlo[QKVN];          // v [B,H,HD,S] (transposed)
__device__ bf16 g_yhi[M_*D_], g_ylo[M_*D_];          // attn out [M,K]

extern __shared__ char smem_raw[];

// ---------------------------------------------------------------------------
__device__ __forceinline__ void split_bf(float v, bf16& h, bf16& l) {
    h = __float2bfloat16_rn(v);
    l = __float2bfloat16_rn(v - __bfloat162float(h));
}
__device__ __forceinline__ uint32_t pk2f(float a, float b) {
    __nv_bfloat162 t(__float2bfloat16_rn(a), __float2bfloat16_rn(b));
    return *reinterpret_cast<uint32_t*>(&t);
}
__device__ __forceinline__ uint32_t pk2(bf16 a, bf16 b) {
    __nv_bfloat162 t(a, b);
    return *reinterpret_cast<uint32_t*>(&t);
}
__device__ __forceinline__ void mma16816(float* c, const uint32_t* a, const uint32_t* b) {
    asm volatile(
        "mma.sync.aligned.m16n8k16.row.col.f32.bf16.bf16.f32 "
        "{%0,%1,%2,%3}, {%4,%5,%6,%7}, {%8,%9}, {%0,%1,%2,%3};"
        : "+f"(c[0]), "+f"(c[1]), "+f"(c[2]), "+f"(c[3])
        : "r"(a[0]), "r"(a[1]), "r"(a[2]), "r"(a[3]), "r"(b[0]), "r"(b[1]));
}
__device__ __forceinline__ uint32_t smem_u32(const void* p) {
    uint32_t a;
    asm("{ .reg .u64 t; cvta.to.shared.u64 t, %1; cvt.u32.u64 %0, t; }" : "=r"(a) : "l"(p));
    return a;
}
#define CP16(dst, src) \
    asm volatile("cp.async.cg.shared.global [%0], [%1], 16;" :: "r"(dst), "l"(src))
#define CP_COMMIT() asm volatile("cp.async.commit_group;")
#define CP_WAIT1()  asm volatile("cp.async.wait_group 1;")
#define CP_WAIT0()  asm volatile("cp.async.wait_group 0;")

// ===========================================================================
// Conversion kernels
// ===========================================================================
__global__ void conv_split(const float* __restrict__ src, bf16* __restrict__ hi,
                           bf16* __restrict__ lo, int n4)
{
    int i = blockIdx.x * 256 + threadIdx.x;
    if (i >= n4) return;
    float4 v = reinterpret_cast<const float4*>(src)[i];
    bf16 h0,h1,h2,h3,l0,l1,l2,l3;
    split_bf(v.x,h0,l0); split_bf(v.y,h1,l1);
    split_bf(v.z,h2,l2); split_bf(v.w,h3,l3);
    uint2 hw; hw.x = pk2(h0,h1); hw.y = pk2(h2,h3);
    uint2 lw; lw.x = pk2(l0,l1); lw.y = pk2(l2,l3);
    *reinterpret_cast<uint2*>(hi + i*4) = hw;
    *reinterpret_cast<uint2*>(lo + i*4) = lw;
}

// W [K=1024, N] -> hiT/loT [N, K]; CTA handles 64k x 64n tile.
__global__ __launch_bounds__(256) void conv_wT(const float* __restrict__ W,
                                               bf16* __restrict__ hiT,
                                               bf16* __restrict__ loT, int N)
{
    __shared__ bf16 sh[64*66], sl[64*66];   // [n][k], stride 66
    const int n0 = blockIdx.x * 64;
    const int k0 = blockIdx.y * 64;
    const int tid = threadIdx.x;
    #pragma unroll
    for (int i = 0; i < 4; i++) {
        int idx = tid + i * 256;            // 0..1023 float4s
        int r = idx >> 4;                   // k row 0..63
        int c4 = idx & 15;                  // float4 within 64 n
        float4 v = *reinterpret_cast<const float4*>(W + (size_t)(k0 + r) * N + n0 + c4*4);
        bf16 h, l;
        split_bf(v.x,h,l); sh[(c4*4+0)*66 + r] = h; sl[(c4*4+0)*66 + r] = l;
        split_bf(v.y,h,l); sh[(c4*4+1)*66 + r] = h; sl[(c4*4+1)*66 + r] = l;
        split_bf(v.z,h,l); sh[(c4*4+2)*66 + r] = h; sl[(c4*4+2)*66 + r] = l;
        split_bf(v.w,h,l); sh[(c4*4+3)*66 + r] = h; sl[(c4*4+3)*66 + r] = l;
    }
    __syncthreads();
    const uint32_t* sh32 = reinterpret_cast<const uint32_t*>(sh);
    const uint32_t* sl32 = reinterpret_cast<const uint32_t*>(sl);
    #pragma unroll
    for (int i = 0; i < 2; i++) {
        int idx = tid + i * 256;            // 0..511 chunks
        int n = idx >> 3;                   // 0..63
        int ch = idx & 7;                   // 16B chunk (8 bf16)
        int sb = (n*66 + ch*8) >> 1;
        uint4 hv = make_uint4(sh32[sb], sh32[sb+1], sh32[sb+2], sh32[sb+3]);
        uint4 lv = make_uint4(sl32[sb], sl32[sb+1], sl32[sb+2], sl32[sb+3]);
        size_t o = (size_t)(n0 + n) * D_ + k0 + ch*8;
        *reinterpret_cast<uint4*>(hiT + o) = hv;
        *reinterpret_cast<uint4*>(loT + o) = lv;
    }
}

// ===========================================================================
// GEMM on pre-split planes, cp.async double-buffered.
// C[M x N_TOTAL] = A @ W^T-planes + bias. Tile 128x128, KC=64, 2 stages.
// ===========================================================================
#define LDK 72
#define PLANE_B (128 * LDK * 2)               // 18432 bytes per plane
#define STAGE_B (4 * PLANE_B)                 // 73728
#define SMEM_GEMM (2 * STAGE_B)               // 147456
#define OFA_HI 0
#define OFA_LO PLANE_B
#define OFB_HI (2*PLANE_B)
#define OFB_LO (3*PLANE_B)

template<int N_TOTAL, bool QKV>
__global__ __launch_bounds__(256)
void gemm_mma(const bf16* __restrict__ Ahi, const bf16* __restrict__ Alo,
              const bf16* __restrict__ BhiT, const bf16* __restrict__ BloT,
              const float* __restrict__ bias, float* __restrict__ out)
{
    const uint32_t sbase = smem_u32(smem_raw);
    const int tid = threadIdx.x;
    const int wid = tid >> 5;
    const int lane = tid & 31;
    const int grp = lane >> 2;
    const int tig = lane & 3;
    const int wm = (wid >> 2) * 64;
    const int wn = (wid & 3) * 32;
    const int bm = blockIdx.y * 128;
    const int bn = blockIdx.x * 128;

    const int lrow = tid >> 3;       // 0..31? no: 256 threads, idx>>3 below
    (void)lrow;

    auto load_stage = [&](int c, int st) {
        uint32_t sb = sbase + st * STAGE_B;
        #pragma unroll
        for (int i = 0; i < 4; i++) {
            int idx = tid + i * 256;          // 0..1023
            int row = idx >> 3;               // 0..127
            int ch  = idx & 7;                // 16B chunk
            uint32_t so = row * (LDK*2) + ch * 16;
            size_t ga = (size_t)(bm + row) * D_ + c * 64 + ch * 8;
            size_t gb = (size_t)(bn + row) * D_ + c * 64 + ch * 8;
            CP16(sb + OFA_HI + so, Ahi + ga);
            CP16(sb + OFA_LO + so, Alo + ga);
            CP16(sb + OFB_HI + so, BhiT + gb);
            CP16(sb + OFB_LO + so, BloT + gb);
        }
        CP_COMMIT();
    };

    float acc[4][4][4];
    #pragma unroll
    for (int i = 0; i < 4; i++)
        #pragma unroll
        for (int j = 0; j < 4; j++)
            #pragma unroll
            for (int q = 0; q < 4; q++) acc[i][j][q] = 0.f;

    load_stage(0, 0);
    load_stage(1, 1);

    for (int c = 0; c < 16; c++) {
        if (c < 15) { CP_WAIT1(); } else { CP_WAIT0(); }
        __syncthreads();

        const int st = c & 1;
        const uint32_t* sA_hi = reinterpret_cast<const uint32_t*>(smem_raw + st*STAGE_B + OFA_HI);
        const uint32_t* sA_lo = reinterpret_cast<const uint32_t*>(smem_raw + st*STAGE_B + OFA_LO);
        const uint32_t* sB_hi = reinterpret_cast<const uint32_t*>(smem_raw + st*STAGE_B + OFB_HI);
        const uint32_t* sB_lo = reinterpret_cast<const uint32_t*>(smem_raw + st*STAGE_B + OFB_LO);

        #pragma unroll
        for (int ks = 0; ks < 4; ks++) {
            const int k0 = ks * 16;
            uint32_t bh[4][2], bl[4][2];
            #pragma unroll
            for (int nt = 0; nt < 4; nt++) {
                int ob = ((wn + nt*8 + grp) * LDK + k0 + 2*tig) >> 1;
                bh[nt][0] = sB_hi[ob];     bl[nt][0] = sB_lo[ob];
                bh[nt][1] = sB_hi[ob + 4]; bl[nt][1] = sB_lo[ob + 4];
            }
            #pragma unroll
            for (int mt = 0; mt < 4; mt++) {
                int oa  = ((wm + mt*16 + grp) * LDK + k0 + 2*tig) >> 1;
                int oa8 = oa + (8 * LDK >> 1);
                uint32_t ah[4], al[4];
                ah[0] = sA_hi[oa];     ah[1] = sA_hi[oa8];
                ah[2] = sA_hi[oa + 4]; ah[3] = sA_hi[oa8 + 4];
                al[0] = sA_lo[oa];     al[1] = sA_lo[oa8];
                al[2] = sA_lo[oa + 4]; al[3] = sA_lo[oa8 + 4];
                #pragma unroll
                for (int nt = 0; nt < 4; nt++) {
                    mma16816(acc[mt][nt], ah, bh[nt]);
                    mma16816(acc[mt][nt], ah, bl[nt]);
                    mma16816(acc[mt][nt], al, bh[nt]);
                }
            }
        }
        __syncthreads();
        if (c + 2 < 16) load_stage(c + 2, st);
    }

    // ---- Epilogue ----
    #pragma unroll
    for (int mt = 0; mt < 4; mt++) {
        #pragma unroll
        for (int half = 0; half < 2; half++) {
            int m = bm + wm + mt * 16 + grp + half * 8;
            #pragma unroll
            for (int nt = 0; nt < 4; nt++) {
                int n = bn + wn + nt * 8 + 2 * tig;
                float v0 = acc[mt][nt][half*2 + 0] + bias[n];
                float v1 = acc[mt][nt][half*2 + 1] + bias[n + 1];
                if (QKV) {
                    int which = n >> 10;
                    int d0 = n & 1023;
                    int h = d0 >> 6, hd = d0 & 63;
                    int b = m >> 11, s = m & 2047;
                    bf16 h0,l0,h1,l1;
                    split_bf(v0,h0,l0); split_bf(v1,h1,l1);
                    if (which == 2) {
                        size_t o = ((size_t)(b*H_ + h)*HD_ + hd)*S_ + s;
                        g_vThi[o] = h0; g_vTlo[o] = l0;
                        g_vThi[o + S_] = h1; g_vTlo[o + S_] = l1;
                    } else {
                        size_t o = (((size_t)(b*H_ + h)*S_) + s)*HD_ + hd;
                        bf16* dhi = (which == 0) ? g_qhi : g_khi;
                        bf16* dlo = (which == 0) ? g_qlo : g_klo;
                        *reinterpret_cast<uint32_t*>(dhi + o) = pk2(h0, h1);
                        *reinterpret_cast<uint32_t*>(dlo + o) = pk2(l0, l1);
                    }
                } else {
                    *reinterpret_cast<float2*>(out + (size_t)m * N_TOTAL + n) =
                        make_float2(v0, v1);
                }
            }
        }
    }
}

// ===========================================================================
// Flash attention on pre-split planes. CTA = (b,h) x 64-q tile, 4 warps.
// smem: K hi/lo + V hi/lo, stride 72, cp.async single-stage.
// ===========================================================================
#define APL (64 * LDK * 2)                    // 9216 bytes per plane
#define SMEM_ATTN (4 * APL)                   // 36864

__global__ __launch_bounds__(128) void attn_mma()
{
    const int qt = blockIdx.x;
    const int bh = blockIdx.y;
    const int b  = bh >> 4;
    const int h  = bh & 15;
    const size_t head = (size_t)bh * S_ * HD_;

    const int tid = threadIdx.x;
    const int wid = tid >> 5;
    const int lane = tid & 31;
    const int grp = lane >> 2;
    const int tig = lane & 3;
    const int wm = wid * 16;

    const uint32_t sbase = smem_u32(smem_raw);
    const uint32_t uKhi = sbase, uKlo = sbase + APL;
    const uint32_t uVhi = sbase + 2*APL, uVlo = sbase + 3*APL;
    const uint32_t* sKhi32 = reinterpret_cast<const uint32_t*>(smem_raw);
    const uint32_t* sKlo32 = reinterpret_cast<const uint32_t*>(smem_raw + APL);
    const uint32_t* sVhi32 = reinterpret_cast<const uint32_t*>(smem_raw + 2*APL);
    const uint32_t* sVlo32 = reinterpret_cast<const uint32_t*>(smem_raw + 3*APL);

    // ---- Q tile staged through K planes ----
    #pragma unroll
    for (int i = 0; i < 4; i++) {
        int idx = tid + i * 128;              // 0..511
        int row = idx >> 3, ch = idx & 7;
        uint32_t so = row * (LDK*2) + ch * 16;
        size_t g = head + (size_t)(qt*64 + row) * HD_ + ch * 8;
        CP16(uKhi + so, g_qhi + g);
        CP16(uKlo + so, g_qlo + g);
    }
    CP_COMMIT(); CP_WAIT0();
    __syncthreads();

    uint32_t qh[4][4], ql[4][4];
    #pragma unroll
    for (int ks = 0; ks < 4; ks++) {
        int oa  = ((wm + grp) * LDK + ks*16 + 2*tig) >> 1;
        int oa8 = oa + (8 * LDK >> 1);
        qh[ks][0] = sKhi32[oa];     qh[ks][1] = sKhi32[oa8];
        qh[ks][2] = sKhi32[oa + 4]; qh[ks][3] = sKhi32[oa8 + 4];
        ql[ks][0] = sKlo32[oa];     ql[ks][1] = sKlo32[oa8];
        ql[ks][2] = sKlo32[oa + 4]; ql[ks][3] = sKlo32[oa8 + 4];
    }

    float o[8][4];
    #pragma unroll
    for (int nt = 0; nt < 8; nt++)
        #pragma unroll
        for (int q = 0; q < 4; q++) o[nt][q] = 0.f;
    float mrow[2] = {-1e30f, -1e30f};
    float lrow[2] = {0.f, 0.f};
    const float scale = 0.125f;

    for (int kt = 0; kt <= qt; kt++) {
        __syncthreads();                      // prev tile reads done
        #pragma unroll
        for (int i = 0; i < 4; i++) {
            int idx = tid + i * 128;
            int row = idx >> 3, ch = idx & 7;
            uint32_t so = row * (LDK*2) + ch * 16;
            size_t gk = head + (size_t)(kt*64 + row) * HD_ + ch * 8;
            size_t gv = head + (size_t)row * S_ + kt*64 + ch * 8;   // vT [hd][s]
            CP16(uKhi + so, g_khi + gk);
            CP16(uKlo + so, g_klo + gk);
            CP16(uVhi + so, g_vThi + gv);
            CP16(uVlo + so, g_vTlo + gv);
        }
        CP_COMMIT(); CP_WAIT0();
        __syncthreads();

        // ---- S = Q K^T ----
        float s[8][4];
        #pragma unroll
        for (int nt = 0; nt < 8; nt++)
            #pragma unroll
            for (int q = 0; q < 4; q++) s[nt][q] = 0.f;
        #pragma unroll
        for (int nt = 0; nt < 8; nt++) {
            #pragma unroll
            for (int ks = 0; ks < 4; ks++) {
                int ob = ((nt*8 + grp) * LDK + ks*16 + 2*tig) >> 1;
                uint32_t bhf[2], blf[2];
                bhf[0] = sKhi32[ob]; bhf[1] = sKhi32[ob + 4];
                blf[0] = sKlo32[ob]; blf[1] = sKlo32[ob + 4];
                mma16816(s[nt], qh[ks], bhf);
                mma16816(s[nt], qh[ks], blf);
                mma16816(s[nt], ql[ks], bhf);
            }
        }

        // ---- scale + causal mask ----
        #pragma unroll
        for (int nt = 0; nt < 8; nt++)
            #pragma unroll
            for (int q = 0; q < 4; q++) s[nt][q] *= scale;
        if (kt == qt) {
            #pragma unroll
            for (int nt = 0; nt < 8; nt++) {
                int col = nt * 8 + 2 * tig;
                int r0 = wm + grp, r1 = r0 + 8;
                if (col     > r0) s[nt][0] = -1e30f;
                if (col + 1 > r0) s[nt][1] = -1e30f;
                if (col     > r1) s[nt][2] = -1e30f;
                if (col + 1 > r1) s[nt][3] = -1e30f;
            }
        }

        // ---- online softmax ----
        float mx0 = -1e30f, mx1 = -1e30f;
        #pragma unroll
        for (int nt = 0; nt < 8; nt++) {
            mx0 = fmaxf(mx0, fmaxf(s[nt][0], s[nt][1]));
            mx1 = fmaxf(mx1, fmaxf(s[nt][2], s[nt][3]));
        }
        mx0 = fmaxf(mx0, __shfl_xor_sync(0xffffffffu, mx0, 1));
        mx0 = fmaxf(mx0, __shfl_xor_sync(0xffffffffu, mx0, 2));
        mx1 = fmaxf(mx1, __shfl_xor_sync(0xffffffffu, mx1, 1));
        mx1 = fmaxf(mx1, __shfl_xor_sync(0xffffffffu, mx1, 2));
        float mn0 = fmaxf(mrow[0], mx0);
        float mn1 = fmaxf(mrow[1], mx1);
        float a0 = __expf(mrow[0] - mn0);
        float a1 = __expf(mrow[1] - mn1);
        float sum0 = 0.f, sum1 = 0.f;
        #pragma unroll
        for (int nt = 0; nt < 8; nt++) {
            s[nt][0] = __expf(s[nt][0] - mn0);
            s[nt][1] = __expf(s[nt][1] - mn0);
            s[nt][2] = __expf(s[nt][2] - mn1);
            s[nt][3] = __expf(s[nt][3] - mn1);
            sum0 += s[nt][0] + s[nt][1];
            sum1 += s[nt][2] + s[nt][3];
        }
        sum0 += __shfl_xor_sync(0xffffffffu, sum0, 1);
        sum0 += __shfl_xor_sync(0xffffffffu, sum0, 2);
        sum1 += __shfl_xor_sync(0xffffffffu, sum1, 1);
        sum1 += __shfl_xor_sync(0xffffffffu, sum1, 2);
        lrow[0] = lrow[0] * a0 + sum0;
        lrow[1] = lrow[1] * a1 + sum1;
        mrow[0] = mn0; mrow[1] = mn1;
        #pragma unroll
        for (int nt = 0; nt < 8; nt++) {
            o[nt][0] *= a0; o[nt][1] *= a0;
            o[nt][2] *= a1; o[nt][3] *= a1;
        }

        // ---- pack P fragments ----
        uint32_t ph[4][4], pl[4][4];
        #pragma unroll
        for (int ks = 0; ks < 4; ks++) {
            const float* c0 = s[2*ks];
            const float* c1 = s[2*ks + 1];
            ph[ks][0] = pk2f(c0[0], c0[1]);
            ph[ks][1] = pk2f(c0[2], c0[3]);
            ph[ks][2] = pk2f(c1[0], c1[1]);
            ph[ks][3] = pk2f(c1[2], c1[3]);
            float r00 = c0[0] - __bfloat162float(__float2bfloat16_rn(c0[0]));
            float r01 = c0[1] - __bfloat162float(__float2bfloat16_rn(c0[1]));
            float r02 = c0[2] - __bfloat162float(__float2bfloat16_rn(c0[2]));
            float r03 = c0[3] - __bfloat162float(__float2bfloat16_rn(c0[3]));
            float r10 = c1[0] - __bfloat162float(__float2bfloat16_rn(c1[0]));
            float r11 = c1[1] - __bfloat162float(__float2bfloat16_rn(c1[1]));
            float r12 = c1[2] - __bfloat162float(__float2bfloat16_rn(c1[2]));
            float r13 = c1[3] - __bfloat162float(__float2bfloat16_rn(c1[3]));
            pl[ks][0] = pk2f(r00, r01);
            pl[ks][1] = pk2f(r02, r03);
            pl[ks][2] = pk2f(r10, r11);
            pl[ks][3] = pk2f(r12, r13);
        }

        // ---- O += P V ----
        #pragma unroll
        for (int nt = 0; nt < 8; nt++) {
            #pragma unroll
            for (int ks = 0; ks < 4; ks++) {
                int ob = (nt*8 + grp) * (LDK/2) + ks*8 + tig;
                uint32_t vh[2], vl[2];
                vh[0] = sVhi32[ob]; vh[1] = sVhi32[ob + 4];
                vl[0] = sVlo32[ob]; vl[1] = sVlo32[ob + 4];
                mma16816(o[nt], ph[ks], vh);
                mma16816(o[nt], ph[ks], vl);
                mma16816(o[nt], pl[ks], vh);
            }
        }
    }

    // ---- finalize: write y hi/lo planes ----
    float inv0 = 1.0f / lrow[0];
    float inv1 = 1.0f / lrow[1];
    int r0 = qt * 64 + wm + grp;
    int r1 = r0 + 8;
    #pragma unroll
    for (int nt = 0; nt < 8; nt++) {
        int col = h * HD_ + nt * 8 + 2 * tig;
        float y00 = o[nt][0] * inv0, y01 = o[nt][1] * inv0;
        float y10 = o[nt][2] * inv1, y11 = o[nt][3] * inv1;
        bf16 h0,l0,h1,l1;
        size_t o0 = ((size_t)b * S_ + r0) * D_ + col;
        size_t o1 = ((size_t)b * S_ + r1) * D_ + col;
        split_bf(y00,h0,l0); split_bf(y01,h1,l1);
        *reinterpret_cast<uint32_t*>(g_yhi + o0) = pk2(h0,h1);
        *reinterpret_cast<uint32_t*>(g_ylo + o0) = pk2(l0,l1);
        split_bf(y10,h0,l0); split_bf(y11,h1,l1);
        *reinterpret_cast<uint32_t*>(g_yhi + o1) = pk2(h0,h1);
        *reinterpret_cast<uint32_t*>(g_ylo + o1) = pk2(l0,l1);
    }
}

// ---------------------------------------------------------------------------
extern "C" void kernel_launch(void* const* d_in, const int* in_sizes, int n_in,
                              void* d_out, int out_size)
{
    const float* x      = nullptr;
    const float* W_attn = nullptr;
    const float* b_attn = nullptr;
    const float* W_proj = nullptr;
    const float* b_proj = nullptr;
    for (int i = 0; i < n_in; i++) {
        switch (in_sizes[i]) {
            case B_*S_*D_:    x      = (const float*)d_in[i]; break;
            case D_*3*D_:     W_attn = (const float*)d_in[i]; break;
            case 3*D_:        b_attn = (const float*)d_in[i]; break;
            case D_*D_:       W_proj = (const float*)d_in[i]; break;
            case D_:          b_proj = (const float*)d_in[i]; break;
            default: break;
        }
    }
    float* out = (float*)d_out;

    // Device addresses of plane globals (host shadow symbols are NOT device ptrs)
    void *xhi, *xlo, *wahiT, *waloT, *wphiT, *wploT, *yhi, *ylo;
    cudaGetSymbolAddress(&xhi, g_xhi);     cudaGetSymbolAddress(&xlo, g_xlo);
    cudaGetSymbolAddress(&wahiT, g_wahiT); cudaGetSymbolAddress(&waloT, g_waloT);
    cudaGetSymbolAddress(&wphiT, g_wphiT); cudaGetSymbolAddress(&wploT, g_wploT);
    cudaGetSymbolAddress(&yhi, g_yhi);     cudaGetSymbolAddress(&ylo, g_ylo);

    cudaFuncSetAttribute(gemm_mma<N_QKV, true>,
                         cudaFuncAttributeMaxDynamicSharedMemorySize, SMEM_GEMM);
    cudaFuncSetAttribute(gemm_mma<D_, false>,
                         cudaFuncAttributeMaxDynamicSharedMemorySize, SMEM_GEMM);
    cudaFuncSetAttribute(attn_mma,
                         cudaFuncAttributeMaxDynamicSharedMemorySize, SMEM_ATTN);

    // Conversions
    conv_split<<<(M_*D_/4 + 255)/256, 256>>>(x, (bf16*)xhi, (bf16*)xlo, M_*D_/4);
    conv_wT<<<dim3(N_QKV/64, D_/64), 256>>>(W_attn, (bf16*)wahiT, (bf16*)waloT, N_QKV);
    conv_wT<<<dim3(D_/64, D_/64), 256>>>(W_proj, (bf16*)wphiT, (bf16*)wploT, D_);

    // QKV
    dim3 g1(N_QKV / 128, M_ / 128);
    gemm_mma<N_QKV, true><<<g1, 256, SMEM_GEMM>>>(
        (const bf16*)xhi, (const bf16*)xlo,
        (const bf16*)wahiT, (const bf16*)waloT, b_attn, nullptr);

    // Attention
    dim3 g2(S_ / 64, B_ * H_);
    attn_mma<<<g2, 128, SMEM_ATTN>>>();

    // Projection
    dim3 g3(D_ / 128, M_ / 128);
    gemm_mma<D_, false><<<g3, 256, SMEM_GEMM>>>(
        (const bf16*)yhi, (const bf16*)ylo,
        (const bf16*)wphiT, (const bf16*)wploT, b_proj, out);
}

// round 9
// speedup vs baseline: 3.0717x; 1.0054x over previous
#include <cuda_runtime.h>
#include <cuda_bf16.h>
#include <stdint.h>

#define B_ 4
#define S_ 2048
#define D_ 1024
#define H_ 16
#define HD_ 64
#define M_ (B_*S_)      // 8192
#define N_QKV 3072
#define QKVN (B_*H_*S_*HD_)   // 8388608

typedef __nv_bfloat16 bf16;

// ---- Pre-split bf16 hi/lo planes (device globals; allocation-free) ----
__device__ bf16 g_xhi[M_*D_],    g_xlo[M_*D_];       // x        [M,K]
__device__ bf16 g_wahiT[N_QKV*D_], g_waloT[N_QKV*D_];// W_attn^T [N,K]
__device__ bf16 g_wphiT[D_*D_],  g_wploT[D_*D_];     // W_proj^T [N,K]
__device__ bf16 g_qhi[QKVN], g_qlo[QKVN];            // q [B,H,S,HD]
__device__ bf16 g_khi[QKVN], g_klo[QKVN];            // k [B,H,S,HD]
__device__ bf16 g_vThi[QKVN], g_vTlo[QKVN];          // v [B,H,HD,S] (transposed)
__device__ bf16 g_yhi[M_*D_], g_ylo[M_*D_];          // attn out [M,K]

extern __shared__ char smem_raw[];

// ---------------------------------------------------------------------------
__device__ __forceinline__ void split_bf(float v, bf16& h, bf16& l) {
    h = __float2bfloat16_rn(v);
    l = __float2bfloat16_rn(v - __bfloat162float(h));
}
__device__ __forceinline__ uint32_t pk2f(float a, float b) {
    __nv_bfloat162 t(__float2bfloat16_rn(a), __float2bfloat16_rn(b));
    return *reinterpret_cast<uint32_t*>(&t);
}
__device__ __forceinline__ uint32_t pk2(bf16 a, bf16 b) {
    __nv_bfloat162 t(a, b);
    return *reinterpret_cast<uint32_t*>(&t);
}
__device__ __forceinline__ void mma16816(float* c, const uint32_t* a, const uint32_t* b) {
    asm volatile(
        "mma.sync.aligned.m16n8k16.row.col.f32.bf16.bf16.f32 "
        "{%0,%1,%2,%3}, {%4,%5,%6,%7}, {%8,%9}, {%0,%1,%2,%3};"
        : "+f"(c[0]), "+f"(c[1]), "+f"(c[2]), "+f"(c[3])
        : "r"(a[0]), "r"(a[1]), "r"(a[2]), "r"(a[3]), "r"(b[0]), "r"(b[1]));
}
__device__ __forceinline__ uint32_t smem_u32(const void* p) {
    uint32_t a;
    asm("{ .reg .u64 t; cvta.to.shared.u64 t, %1; cvt.u32.u64 %0, t; }" : "=r"(a) : "l"(p));
    return a;
}
#define CP16(dst, src) \
    asm volatile("cp.async.cg.shared.global [%0], [%1], 16;" :: "r"(dst), "l"(src))
#define CP_COMMIT() asm volatile("cp.async.commit_group;")
#define CP_WAIT1()  asm volatile("cp.async.wait_group 1;")
#define CP_WAIT0()  asm volatile("cp.async.wait_group 0;")

// ===========================================================================
// Conversion kernels
// ===========================================================================
__global__ void conv_split(const float* __restrict__ src, bf16* __restrict__ hi,
                           bf16* __restrict__ lo, int n4)
{
    int i = blockIdx.x * 256 + threadIdx.x;
    if (i >= n4) return;
    float4 v = reinterpret_cast<const float4*>(src)[i];
    bf16 h0,h1,h2,h3,l0,l1,l2,l3;
    split_bf(v.x,h0,l0); split_bf(v.y,h1,l1);
    split_bf(v.z,h2,l2); split_bf(v.w,h3,l3);
    uint2 hw; hw.x = pk2(h0,h1); hw.y = pk2(h2,h3);
    uint2 lw; lw.x = pk2(l0,l1); lw.y = pk2(l2,l3);
    *reinterpret_cast<uint2*>(hi + i*4) = hw;
    *reinterpret_cast<uint2*>(lo + i*4) = lw;
}

// W [K=1024, N] -> hiT/loT [N, K]; CTA handles 64k x 64n tile.
__global__ __launch_bounds__(256) void conv_wT(const float* __restrict__ W,
                                               bf16* __restrict__ hiT,
                                               bf16* __restrict__ loT, int N)
{
    __shared__ bf16 sh[64*66], sl[64*66];   // [n][k], stride 66
    const int n0 = blockIdx.x * 64;
    const int k0 = blockIdx.y * 64;
    const int tid = threadIdx.x;
    #pragma unroll
    for (int i = 0; i < 4; i++) {
        int idx = tid + i * 256;
        int r = idx >> 4;
        int c4 = idx & 15;
        float4 v = *reinterpret_cast<const float4*>(W + (size_t)(k0 + r) * N + n0 + c4*4);
        bf16 h, l;
        split_bf(v.x,h,l); sh[(c4*4+0)*66 + r] = h; sl[(c4*4+0)*66 + r] = l;
        split_bf(v.y,h,l); sh[(c4*4+1)*66 + r] = h; sl[(c4*4+1)*66 + r] = l;
        split_bf(v.z,h,l); sh[(c4*4+2)*66 + r] = h; sl[(c4*4+2)*66 + r] = l;
        split_bf(v.w,h,l); sh[(c4*4+3)*66 + r] = h; sl[(c4*4+3)*66 + r] = l;
    }
    __syncthreads();
    const uint32_t* sh32 = reinterpret_cast<const uint32_t*>(sh);
    const uint32_t* sl32 = reinterpret_cast<const uint32_t*>(sl);
    #pragma unroll
    for (int i = 0; i < 2; i++) {
        int idx = tid + i * 256;
        int n = idx >> 3;
        int ch = idx & 7;
        int sb = (n*66 + ch*8) >> 1;
        uint4 hv = make_uint4(sh32[sb], sh32[sb+1], sh32[sb+2], sh32[sb+3]);
        uint4 lv = make_uint4(sl32[sb], sl32[sb+1], sl32[sb+2], sl32[sb+3]);
        size_t o = (size_t)(n0 + n) * D_ + k0 + ch*8;
        *reinterpret_cast<uint4*>(hiT + o) = hv;
        *reinterpret_cast<uint4*>(loT + o) = lv;
    }
}

// ===========================================================================
// GEMM: KC=32 stages, 2-stage cp.async, 2 CTAs/SM.
// Tile 128x128, 8 warps (2m x 4n), warp 64x32.
// ===========================================================================
#define LDK2 40
#define PLANE2 (128 * LDK2 * 2)               // 10240 bytes
#define STAGE2 (4 * PLANE2)                   // 40960
#define SMEM_GEMM (2 * STAGE2)                // 81920
#define OF2_AHI 0
#define OF2_ALO PLANE2
#define OF2_BHI (2*PLANE2)
#define OF2_BLO (3*PLANE2)

template<int N_TOTAL, bool QKV>
__global__ __launch_bounds__(256, 2)
void gemm_mma(const bf16* __restrict__ Ahi, const bf16* __restrict__ Alo,
              const bf16* __restrict__ BhiT, const bf16* __restrict__ BloT,
              const float* __restrict__ bias, float* __restrict__ out)
{
    const uint32_t sbase = smem_u32(smem_raw);
    const int tid = threadIdx.x;
    const int wid = tid >> 5;
    const int lane = tid & 31;
    const int grp = lane >> 2;
    const int tig = lane & 3;
    const int wm = (wid >> 2) * 64;
    const int wn = (wid & 3) * 32;
    const int bm = blockIdx.y * 128;
    const int bn = blockIdx.x * 128;

    auto load_stage = [&](int c, int st) {
        uint32_t sb = sbase + st * STAGE2;
        #pragma unroll
        for (int i = 0; i < 2; i++) {
            int idx = tid + i * 256;          // 0..511
            int row = idx >> 2;               // 0..127
            int ch  = idx & 3;                // 16B chunk (8 bf16 of the 32 k)
            uint32_t so = row * (LDK2*2) + ch * 16;
            size_t ga = (size_t)(bm + row) * D_ + c * 32 + ch * 8;
            size_t gb = (size_t)(bn + row) * D_ + c * 32 + ch * 8;
            CP16(sb + OF2_AHI + so, Ahi + ga);
            CP16(sb + OF2_ALO + so, Alo + ga);
            CP16(sb + OF2_BHI + so, BhiT + gb);
            CP16(sb + OF2_BLO + so, BloT + gb);
        }
        CP_COMMIT();
    };

    float acc[4][4][4];
    #pragma unroll
    for (int i = 0; i < 4; i++)
        #pragma unroll
        for (int j = 0; j < 4; j++)
            #pragma unroll
            for (int q = 0; q < 4; q++) acc[i][j][q] = 0.f;

    load_stage(0, 0);
    load_stage(1, 1);

    for (int c = 0; c < 32; c++) {
        if (c < 31) { CP_WAIT1(); } else { CP_WAIT0(); }
        __syncthreads();

        const int st = c & 1;
        const uint32_t* sA_hi = reinterpret_cast<const uint32_t*>(smem_raw + st*STAGE2 + OF2_AHI);
        const uint32_t* sA_lo = reinterpret_cast<const uint32_t*>(smem_raw + st*STAGE2 + OF2_ALO);
        const uint32_t* sB_hi = reinterpret_cast<const uint32_t*>(smem_raw + st*STAGE2 + OF2_BHI);
        const uint32_t* sB_lo = reinterpret_cast<const uint32_t*>(smem_raw + st*STAGE2 + OF2_BLO);

        #pragma unroll
        for (int ks = 0; ks < 2; ks++) {
            const int k0 = ks * 16;
            uint32_t bh[4][2], bl[4][2];
            #pragma unroll
            for (int nt = 0; nt < 4; nt++) {
                int ob = ((wn + nt*8 + grp) * LDK2 + k0 + 2*tig) >> 1;
                bh[nt][0] = sB_hi[ob];     bl[nt][0] = sB_lo[ob];
                bh[nt][1] = sB_hi[ob + 4]; bl[nt][1] = sB_lo[ob + 4];
            }
            #pragma unroll
            for (int mt = 0; mt < 4; mt++) {
                int oa  = ((wm + mt*16 + grp) * LDK2 + k0 + 2*tig) >> 1;
                int oa8 = oa + (8 * LDK2 >> 1);
                uint32_t ah[4], al[4];
                ah[0] = sA_hi[oa];     ah[1] = sA_hi[oa8];
                ah[2] = sA_hi[oa + 4]; ah[3] = sA_hi[oa8 + 4];
                al[0] = sA_lo[oa];     al[1] = sA_lo[oa8];
                al[2] = sA_lo[oa + 4]; al[3] = sA_lo[oa8 + 4];
                #pragma unroll
                for (int nt = 0; nt < 4; nt++) {
                    mma16816(acc[mt][nt], ah, bh[nt]);
                    mma16816(acc[mt][nt], ah, bl[nt]);
                    mma16816(acc[mt][nt], al, bh[nt]);
                }
            }
        }
        __syncthreads();
        if (c + 2 < 32) load_stage(c + 2, st);
    }

    // ---- Epilogue ----
    #pragma unroll
    for (int mt = 0; mt < 4; mt++) {
        #pragma unroll
        for (int half = 0; half < 2; half++) {
            int m = bm + wm + mt * 16 + grp + half * 8;
            #pragma unroll
            for (int nt = 0; nt < 4; nt++) {
                int n = bn + wn + nt * 8 + 2 * tig;
                float v0 = acc[mt][nt][half*2 + 0] + bias[n];
                float v1 = acc[mt][nt][half*2 + 1] + bias[n + 1];
                if (QKV) {
                    int which = n >> 10;
                    int d0 = n & 1023;
                    int h = d0 >> 6, hd = d0 & 63;
                    int b = m >> 11, s = m & 2047;
                    bf16 h0,l0,h1,l1;
                    split_bf(v0,h0,l0); split_bf(v1,h1,l1);
                    if (which == 2) {
                        size_t o = ((size_t)(b*H_ + h)*HD_ + hd)*S_ + s;
                        g_vThi[o] = h0; g_vTlo[o] = l0;
                        g_vThi[o + S_] = h1; g_vTlo[o + S_] = l1;
                    } else {
                        size_t o = (((size_t)(b*H_ + h)*S_) + s)*HD_ + hd;
                        bf16* dhi = (which == 0) ? g_qhi : g_khi;
                        bf16* dlo = (which == 0) ? g_qlo : g_klo;
                        *reinterpret_cast<uint32_t*>(dhi + o) = pk2(h0, h1);
                        *reinterpret_cast<uint32_t*>(dlo + o) = pk2(l0, l1);
                    }
                } else {
                    *reinterpret_cast<float2*>(out + (size_t)m * N_TOTAL + n) =
                        make_float2(v0, v1);
                }
            }
        }
    }
}

// ===========================================================================
// Flash attention: double-buffered K/V cp.async, 3 CTAs/SM.
// ===========================================================================
#define LDK 72
#define APL (64 * LDK * 2)                    // 9216 bytes per plane
#define STAGE_A (4 * APL)                     // 36864 (Khi,Klo,Vhi,Vlo)
#define SMEM_ATTN (2 * STAGE_A)               // 73728
#define OFK_HI 0
#define OFK_LO APL
#define OFV_HI (2*APL)
#define OFV_LO (3*APL)

__global__ __launch_bounds__(128) void attn_mma()
{
    const int qt = blockIdx.x;
    const int bh = blockIdx.y;
    const int b  = bh >> 4;
    const int h  = bh & 15;
    const size_t head = (size_t)bh * S_ * HD_;

    const int tid = threadIdx.x;
    const int wid = tid >> 5;
    const int lane = tid & 31;
    const int grp = lane >> 2;
    const int tig = lane & 3;
    const int wm = wid * 16;

    const uint32_t sbase = smem_u32(smem_raw);

    auto load_kv = [&](int kt, int st) {
        uint32_t sb = sbase + st * STAGE_A;
        #pragma unroll
        for (int i = 0; i < 4; i++) {
            int idx = tid + i * 128;          // 0..511
            int row = idx >> 3, ch = idx & 7;
            uint32_t so = row * (LDK*2) + ch * 16;
            size_t gk = head + (size_t)(kt*64 + row) * HD_ + ch * 8;
            size_t gv = head + (size_t)row * S_ + kt*64 + ch * 8;   // vT [hd][s]
            CP16(sb + OFK_HI + so, g_khi + gk);
            CP16(sb + OFK_LO + so, g_klo + gk);
            CP16(sb + OFV_HI + so, g_vThi + gv);
            CP16(sb + OFV_LO + so, g_vTlo + gv);
        }
        CP_COMMIT();
    };

    // ---- Q into stage-1 K planes; prefetch kt=0 into stage 0 ----
    {
        uint32_t sb = sbase + STAGE_A;        // stage 1
        #pragma unroll
        for (int i = 0; i < 4; i++) {
            int idx = tid + i * 128;
            int row = idx >> 3, ch = idx & 7;
            uint32_t so = row * (LDK*2) + ch * 16;
            size_t g = head + (size_t)(qt*64 + row) * HD_ + ch * 8;
            CP16(sb + OFK_HI + so, g_qhi + g);
            CP16(sb + OFK_LO + so, g_qlo + g);
        }
        CP_COMMIT();
    }
    load_kv(0, 0);
    CP_WAIT1();                               // Q arrived
    __syncthreads();

    uint32_t qh[4][4], ql[4][4];
    {
        const uint32_t* sQhi = reinterpret_cast<const uint32_t*>(smem_raw + STAGE_A + OFK_HI);
        const uint32_t* sQlo = reinterpret_cast<const uint32_t*>(smem_raw + STAGE_A + OFK_LO);
        #pragma unroll
        for (int ks = 0; ks < 4; ks++) {
            int oa  = ((wm + grp) * LDK + ks*16 + 2*tig) >> 1;
            int oa8 = oa + (8 * LDK >> 1);
            qh[ks][0] = sQhi[oa];     qh[ks][1] = sQhi[oa8];
            qh[ks][2] = sQhi[oa + 4]; qh[ks][3] = sQhi[oa8 + 4];
            ql[ks][0] = sQlo[oa];     ql[ks][1] = sQlo[oa8];
            ql[ks][2] = sQlo[oa + 4]; ql[ks][3] = sQlo[oa8 + 4];
        }
    }
    __syncthreads();                          // Q consumed; stage 1 reusable

    float o[8][4];
    #pragma unroll
    for (int nt = 0; nt < 8; nt++)
        #pragma unroll
        for (int q = 0; q < 4; q++) o[nt][q] = 0.f;
    float mrow[2] = {-1e30f, -1e30f};
    float lrow[2] = {0.f, 0.f};
    const float scale = 0.125f;

    for (int kt = 0; kt <= qt; kt++) {
        const int st = kt & 1;
        if (kt < qt) { load_kv(kt + 1, st ^ 1); CP_WAIT1(); }
        else         { CP_WAIT0(); }
        __syncthreads();

        const uint32_t* sKhi32 = reinterpret_cast<const uint32_t*>(smem_raw + st*STAGE_A + OFK_HI);
        const uint32_t* sKlo32 = reinterpret_cast<const uint32_t*>(smem_raw + st*STAGE_A + OFK_LO);
        const uint32_t* sVhi32 = reinterpret_cast<const uint32_t*>(smem_raw + st*STAGE_A + OFV_HI);
        const uint32_t* sVlo32 = reinterpret_cast<const uint32_t*>(smem_raw + st*STAGE_A + OFV_LO);

        // ---- S = Q K^T ----
        float s[8][4];
        #pragma unroll
        for (int nt = 0; nt < 8; nt++)
            #pragma unroll
            for (int q = 0; q < 4; q++) s[nt][q] = 0.f;
        #pragma unroll
        for (int nt = 0; nt < 8; nt++) {
            #pragma unroll
            for (int ks = 0; ks < 4; ks++) {
                int ob = ((nt*8 + grp) * LDK + ks*16 + 2*tig) >> 1;
                uint32_t bhf[2], blf[2];
                bhf[0] = sKhi32[ob]; bhf[1] = sKhi32[ob + 4];
                blf[0] = sKlo32[ob]; blf[1] = sKlo32[ob + 4];
                mma16816(s[nt], qh[ks], bhf);
                mma16816(s[nt], qh[ks], blf);
                mma16816(s[nt], ql[ks], bhf);
            }
        }

        // ---- scale + causal mask ----
        #pragma unroll
        for (int nt = 0; nt < 8; nt++)
            #pragma unroll
            for (int q = 0; q < 4; q++) s[nt][q] *= scale;
        if (kt == qt) {
            #pragma unroll
            for (int nt = 0; nt < 8; nt++) {
                int col = nt * 8 + 2 * tig;
                int r0 = wm + grp, r1 = r0 + 8;
                if (col     > r0) s[nt][0] = -1e30f;
                if (col + 1 > r0) s[nt][1] = -1e30f;
                if (col     > r1) s[nt][2] = -1e30f;
                if (col + 1 > r1) s[nt][3] = -1e30f;
            }
        }

        // ---- online softmax ----
        float mx0 = -1e30f, mx1 = -1e30f;
        #pragma unroll
        for (int nt = 0; nt < 8; nt++) {
            mx0 = fmaxf(mx0, fmaxf(s[nt][0], s[nt][1]));
            mx1 = fmaxf(mx1, fmaxf(s[nt][2], s[nt][3]));
        }
        mx0 = fmaxf(mx0, __shfl_xor_sync(0xffffffffu, mx0, 1));
        mx0 = fmaxf(mx0, __shfl_xor_sync(0xffffffffu, mx0, 2));
        mx1 = fmaxf(mx1, __shfl_xor_sync(0xffffffffu, mx1, 1));
        mx1 = fmaxf(mx1, __shfl_xor_sync(0xffffffffu, mx1, 2));
        float mn0 = fmaxf(mrow[0], mx0);
        float mn1 = fmaxf(mrow[1], mx1);
        float a0 = __expf(mrow[0] - mn0);
        float a1 = __expf(mrow[1] - mn1);
        float sum0 = 0.f, sum1 = 0.f;
        #pragma unroll
        for (int nt = 0; nt < 8; nt++) {
            s[nt][0] = __expf(s[nt][0] - mn0);
            s[nt][1] = __expf(s[nt][1] - mn0);
            s[nt][2] = __expf(s[nt][2] - mn1);
            s[nt][3] = __expf(s[nt][3] - mn1);
            sum0 += s[nt][0] + s[nt][1];
            sum1 += s[nt][2] + s[nt][3];
        }
        sum0 += __shfl_xor_sync(0xffffffffu, sum0, 1);
        sum0 += __shfl_xor_sync(0xffffffffu, sum0, 2);
        sum1 += __shfl_xor_sync(0xffffffffu, sum1, 1);
        sum1 += __shfl_xor_sync(0xffffffffu, sum1, 2);
        lrow[0] = lrow[0] * a0 + sum0;
        lrow[1] = lrow[1] * a1 + sum1;
        mrow[0] = mn0; mrow[1] = mn1;
        #pragma unroll
        for (int nt = 0; nt < 8; nt++) {
            o[nt][0] *= a0; o[nt][1] *= a0;
            o[nt][2] *= a1; o[nt][3] *= a1;
        }

        // ---- pack P fragments ----
        uint32_t ph[4][4], pl[4][4];
        #pragma unroll
        for (int ks = 0; ks < 4; ks++) {
            const float* c0 = s[2*ks];
            const float* c1 = s[2*ks + 1];
            ph[ks][0] = pk2f(c0[0], c0[1]);
            ph[ks][1] = pk2f(c0[2], c0[3]);
            ph[ks][2] = pk2f(c1[0], c1[1]);
            ph[ks][3] = pk2f(c1[2], c1[3]);
            float r00 = c0[0] - __bfloat162float(__float2bfloat16_rn(c0[0]));
            float r01 = c0[1] - __bfloat162float(__float2bfloat16_rn(c0[1]));
            float r02 = c0[2] - __bfloat162float(__float2bfloat16_rn(c0[2]));
            float r03 = c0[3] - __bfloat162float(__float2bfloat16_rn(c0[3]));
            float r10 = c1[0] - __bfloat162float(__float2bfloat16_rn(c1[0]));
            float r11 = c1[1] - __bfloat162float(__float2bfloat16_rn(c1[1]));
            float r12 = c1[2] - __bfloat162float(__float2bfloat16_rn(c1[2]));
            float r13 = c1[3] - __bfloat162float(__float2bfloat16_rn(c1[3]));
            pl[ks][0] = pk2f(r00, r01);
            pl[ks][1] = pk2f(r02, r03);
            pl[ks][2] = pk2f(r10, r11);
            pl[ks][3] = pk2f(r12, r13);
        }

        // ---- O += P V ----
        #pragma unroll
        for (int nt = 0; nt < 8; nt++) {
            #pragma unroll
            for (int ks = 0; ks < 4; ks++) {
                int ob = (nt*8 + grp) * (LDK/2) + ks*8 + tig;
                uint32_t vh[2], vl[2];
                vh[0] = sVhi32[ob]; vh[1] = sVhi32[ob + 4];
                vl[0] = sVlo32[ob]; vl[1] = sVlo32[ob + 4];
                mma16816(o[nt], ph[ks], vh);
                mma16816(o[nt], ph[ks], vl);
                mma16816(o[nt], pl[ks], vh);
            }
        }
        __syncthreads();                      // stage st reusable next+1 iter
    }

    // ---- finalize: write y hi/lo planes ----
    float inv0 = 1.0f / lrow[0];
    float inv1 = 1.0f / lrow[1];
    int r0 = qt * 64 + wm + grp;
    int r1 = r0 + 8;
    #pragma unroll
    for (int nt = 0; nt < 8; nt++) {
        int col = h * HD_ + nt * 8 + 2 * tig;
        float y00 = o[nt][0] * inv0, y01 = o[nt][1] * inv0;
        float y10 = o[nt][2] * inv1, y11 = o[nt][3] * inv1;
        bf16 h0,l0,h1,l1;
        size_t o0 = ((size_t)b * S_ + r0) * D_ + col;
        size_t o1 = ((size_t)b * S_ + r1) * D_ + col;
        split_bf(y00,h0,l0); split_bf(y01,h1,l1);
        *reinterpret_cast<uint32_t*>(g_yhi + o0) = pk2(h0,h1);
        *reinterpret_cast<uint32_t*>(g_ylo + o0) = pk2(l0,l1);
        split_bf(y10,h0,l0); split_bf(y11,h1,l1);
        *reinterpret_cast<uint32_t*>(g_yhi + o1) = pk2(h0,h1);
        *reinterpret_cast<uint32_t*>(g_ylo + o1) = pk2(l0,l1);
    }
}

// ---------------------------------------------------------------------------
extern "C" void kernel_launch(void* const* d_in, const int* in_sizes, int n_in,
                              void* d_out, int out_size)
{
    const float* x      = nullptr;
    const float* W_attn = nullptr;
    const float* b_attn = nullptr;
    const float* W_proj = nullptr;
    const float* b_proj = nullptr;
    for (int i = 0; i < n_in; i++) {
        switch (in_sizes[i]) {
            case B_*S_*D_:    x      = (const float*)d_in[i]; break;
            case D_*3*D_:     W_attn = (const float*)d_in[i]; break;
            case 3*D_:        b_attn = (const float*)d_in[i]; break;
            case D_*D_:       W_proj = (const float*)d_in[i]; break;
            case D_:          b_proj = (const float*)d_in[i]; break;
            default: break;
        }
    }
    float* out = (float*)d_out;

    void *xhi, *xlo, *wahiT, *waloT, *wphiT, *wploT, *yhi, *ylo;
    cudaGetSymbolAddress(&xhi, g_xhi);     cudaGetSymbolAddress(&xlo, g_xlo);
    cudaGetSymbolAddress(&wahiT, g_wahiT); cudaGetSymbolAddress(&waloT, g_waloT);
    cudaGetSymbolAddress(&wphiT, g_wphiT); cudaGetSymbolAddress(&wploT, g_wploT);
    cudaGetSymbolAddress(&yhi, g_yhi);     cudaGetSymbolAddress(&ylo, g_ylo);

    cudaFuncSetAttribute(gemm_mma<N_QKV, true>,
                         cudaFuncAttributeMaxDynamicSharedMemorySize, SMEM_GEMM);
    cudaFuncSetAttribute(gemm_mma<D_, false>,
                         cudaFuncAttributeMaxDynamicSharedMemorySize, SMEM_GEMM);
    cudaFuncSetAttribute(attn_mma,
                         cudaFuncAttributeMaxDynamicSharedMemorySize, SMEM_ATTN);

    conv_split<<<(M_*D_/4 + 255)/256, 256>>>(x, (bf16*)xhi, (bf16*)xlo, M_*D_/4);
    conv_wT<<<dim3(N_QKV/64, D_/64), 256>>>(W_attn, (bf16*)wahiT, (bf16*)waloT, N_QKV);
    conv_wT<<<dim3(D_/64, D_/64), 256>>>(W_proj, (bf16*)wphiT, (bf16*)wploT, D_);

    dim3 g1(N_QKV / 128, M_ / 128);
    gemm_mma<N_QKV, true><<<g1, 256, SMEM_GEMM>>>(
        (const bf16*)xhi, (const bf16*)xlo,
        (const bf16*)wahiT, (const bf16*)waloT, b_attn, nullptr);

    dim3 g2(S_ / 64, B_ * H_);
    attn_mma<<<g2, 128, SMEM_ATTN>>>();

    dim3 g3(D_ / 128, M_ / 128);
    gemm_mma<D_, false><<<g3, 256, SMEM_GEMM>>>(
        (const bf16*)yhi, (const bf16*)ylo,
        (const bf16*)wphiT, (const bf16*)wploT, b_proj, out);
}

// round 10
// speedup vs baseline: 4.3135x; 1.4043x over previous
#include <cuda_runtime.h>
#include <cuda_fp16.h>
#include <stdint.h>

#define B_ 4
#define S_ 2048
#define D_ 1024
#define H_ 16
#define HD_ 64
#define M_ (B_*S_)      // 8192
#define N_QKV 3072
#define QKVN (B_*H_*S_*HD_)   // 8388608

typedef __half fp16;

// ---- Pre-split fp16 planes (device globals; allocation-free) ----
// A-side operands: hi+lo pair. B-side operands: single truncated plane.
__device__ fp16 g_xhi[M_*D_], g_xlo[M_*D_];          // x        [M,K]  (A)
__device__ fp16 g_waT[N_QKV*D_];                     // W_attn^T [N,K]  (B)
__device__ fp16 g_wpT[D_*D_];                        // W_proj^T [N,K]  (B)
__device__ fp16 g_qhi[QKVN], g_qlo[QKVN];            // q [B,H,S,HD]    (A)
__device__ fp16 g_k1[QKVN];                          // k [B,H,S,HD]    (B)
__device__ fp16 g_vT1[QKVN];                         // v [B,H,HD,S]    (B, transposed)
__device__ fp16 g_yhi[M_*D_], g_ylo[M_*D_];          // attn out [M,K]  (A)

extern __shared__ char smem_raw[];

// ---------------------------------------------------------------------------
__device__ __forceinline__ void split_h(float v, fp16& h, fp16& l) {
    h = __float2half_rn(v);
    l = __float2half_rn(v - __half2float(h));
}
__device__ __forceinline__ uint32_t pk2h(fp16 a, fp16 b) {
    __half2 t(a, b);
    return *reinterpret_cast<uint32_t*>(&t);
}
__device__ __forceinline__ uint32_t pk2hf(float a, float b) {
    __half2 t(__float2half_rn(a), __float2half_rn(b));
    return *reinterpret_cast<uint32_t*>(&t);
}
__device__ __forceinline__ void mma16816h(float* c, const uint32_t* a, const uint32_t* b) {
    asm volatile(
        "mma.sync.aligned.m16n8k16.row.col.f32.f16.f16.f32 "
        "{%0,%1,%2,%3}, {%4,%5,%6,%7}, {%8,%9}, {%0,%1,%2,%3};"
        : "+f"(c[0]), "+f"(c[1]), "+f"(c[2]), "+f"(c[3])
        : "r"(a[0]), "r"(a[1]), "r"(a[2]), "r"(a[3]), "r"(b[0]), "r"(b[1]));
}
__device__ __forceinline__ uint32_t smem_u32(const void* p) {
    uint32_t a;
    asm("{ .reg .u64 t; cvta.to.shared.u64 t, %1; cvt.u32.u64 %0, t; }" : "=r"(a) : "l"(p));
    return a;
}
#define CP16(dst, src) \
    asm volatile("cp.async.cg.shared.global [%0], [%1], 16;" :: "r"(dst), "l"(src))
#define CP_COMMIT() asm volatile("cp.async.commit_group;")
#define CP_WAIT1()  asm volatile("cp.async.wait_group 1;")
#define CP_WAIT0()  asm volatile("cp.async.wait_group 0;")

// ===========================================================================
// Conversion kernels
// ===========================================================================
__global__ void conv_split_h(const float* __restrict__ src, fp16* __restrict__ hi,
                             fp16* __restrict__ lo, int n4)
{
    int i = blockIdx.x * 256 + threadIdx.x;
    if (i >= n4) return;
    float4 v = reinterpret_cast<const float4*>(src)[i];
    fp16 h0,h1,h2,h3,l0,l1,l2,l3;
    split_h(v.x,h0,l0); split_h(v.y,h1,l1);
    split_h(v.z,h2,l2); split_h(v.w,h3,l3);
    uint2 hw; hw.x = pk2h(h0,h1); hw.y = pk2h(h2,h3);
    uint2 lw; lw.x = pk2h(l0,l1); lw.y = pk2h(l2,l3);
    *reinterpret_cast<uint2*>(hi + i*4) = hw;
    *reinterpret_cast<uint2*>(lo + i*4) = lw;
}

// W [K=1024, N] -> single fp16 plane [N, K]; CTA: 64k x 64n tile.
__global__ __launch_bounds__(256) void conv_wT_h(const float* __restrict__ W,
                                                 fp16* __restrict__ T, int N)
{
    __shared__ fp16 sh[64*66];                // [n][k], stride 66
    const int n0 = blockIdx.x * 64;
    const int k0 = blockIdx.y * 64;
    const int tid = threadIdx.x;
    #pragma unroll
    for (int i = 0; i < 4; i++) {
        int idx = tid + i * 256;
        int r = idx >> 4;
        int c4 = idx & 15;
        float4 v = *reinterpret_cast<const float4*>(W + (size_t)(k0 + r) * N + n0 + c4*4);
        sh[(c4*4+0)*66 + r] = __float2half_rn(v.x);
        sh[(c4*4+1)*66 + r] = __float2half_rn(v.y);
        sh[(c4*4+2)*66 + r] = __float2half_rn(v.z);
        sh[(c4*4+3)*66 + r] = __float2half_rn(v.w);
    }
    __syncthreads();
    const uint32_t* sh32 = reinterpret_cast<const uint32_t*>(sh);
    #pragma unroll
    for (int i = 0; i < 2; i++) {
        int idx = tid + i * 256;
        int n = idx >> 3;
        int ch = idx & 7;
        int sb = (n*66 + ch*8) >> 1;
        uint4 hv = make_uint4(sh32[sb], sh32[sb+1], sh32[sb+2], sh32[sb+3]);
        size_t o = (size_t)(n0 + n) * D_ + k0 + ch*8;
        *reinterpret_cast<uint4*>(T + o) = hv;
    }
}

// ===========================================================================
// GEMM fp16 2-term: C = (Ahi+Alo) @ B^T + bias. Tile 128x128, KC=32,
// 2-stage cp.async, 2 CTAs/SM. Planes: Ahi, Alo, B (single).
// ===========================================================================
#define LDK2 40
#define PLANE2 (128 * LDK2 * 2)               // 10240 bytes
#define STAGE2 (3 * PLANE2)                   // 30720
#define SMEM_GEMM (2 * STAGE2)                // 61440
#define OF2_AHI 0
#define OF2_ALO PLANE2
#define OF2_B   (2*PLANE2)

template<int N_TOTAL, bool QKV>
__global__ __launch_bounds__(256, 2)
void gemm_mma(const fp16* __restrict__ Ahi, const fp16* __restrict__ Alo,
              const fp16* __restrict__ BT,
              const float* __restrict__ bias, float* __restrict__ out)
{
    const uint32_t sbase = smem_u32(smem_raw);
    const int tid = threadIdx.x;
    const int wid = tid >> 5;
    const int lane = tid & 31;
    const int grp = lane >> 2;
    const int tig = lane & 3;
    const int wm = (wid >> 2) * 64;
    const int wn = (wid & 3) * 32;
    const int bm = blockIdx.y * 128;
    const int bn = blockIdx.x * 128;

    auto load_stage = [&](int c, int st) {
        uint32_t sb = sbase + st * STAGE2;
        #pragma unroll
        for (int i = 0; i < 2; i++) {
            int idx = tid + i * 256;          // 0..511
            int row = idx >> 2;               // 0..127
            int ch  = idx & 3;                // 16B chunk (8 fp16 of 32 k)
            uint32_t so = row * (LDK2*2) + ch * 16;
            size_t ga = (size_t)(bm + row) * D_ + c * 32 + ch * 8;
            size_t gb = (size_t)(bn + row) * D_ + c * 32 + ch * 8;
            CP16(sb + OF2_AHI + so, Ahi + ga);
            CP16(sb + OF2_ALO + so, Alo + ga);
            CP16(sb + OF2_B   + so, BT  + gb);
        }
        CP_COMMIT();
    };

    float acc[4][4][4];
    #pragma unroll
    for (int i = 0; i < 4; i++)
        #pragma unroll
        for (int j = 0; j < 4; j++)
            #pragma unroll
            for (int q = 0; q < 4; q++) acc[i][j][q] = 0.f;

    load_stage(0, 0);
    load_stage(1, 1);

    for (int c = 0; c < 32; c++) {
        if (c < 31) { CP_WAIT1(); } else { CP_WAIT0(); }
        __syncthreads();

        const int st = c & 1;
        const uint32_t* sA_hi = reinterpret_cast<const uint32_t*>(smem_raw + st*STAGE2 + OF2_AHI);
        const uint32_t* sA_lo = reinterpret_cast<const uint32_t*>(smem_raw + st*STAGE2 + OF2_ALO);
        const uint32_t* sB    = reinterpret_cast<const uint32_t*>(smem_raw + st*STAGE2 + OF2_B);

        #pragma unroll
        for (int ks = 0; ks < 2; ks++) {
            const int k0 = ks * 16;
            uint32_t bh[4][2];
            #pragma unroll
            for (int nt = 0; nt < 4; nt++) {
                int ob = ((wn + nt*8 + grp) * LDK2 + k0 + 2*tig) >> 1;
                bh[nt][0] = sB[ob];
                bh[nt][1] = sB[ob + 4];
            }
            #pragma unroll
            for (int mt = 0; mt < 4; mt++) {
                int oa  = ((wm + mt*16 + grp) * LDK2 + k0 + 2*tig) >> 1;
                int oa8 = oa + (8 * LDK2 >> 1);
                uint32_t ah[4], al[4];
                ah[0] = sA_hi[oa];     ah[1] = sA_hi[oa8];
                ah[2] = sA_hi[oa + 4]; ah[3] = sA_hi[oa8 + 4];
                al[0] = sA_lo[oa];     al[1] = sA_lo[oa8];
                al[2] = sA_lo[oa + 4]; al[3] = sA_lo[oa8 + 4];
                #pragma unroll
                for (int nt = 0; nt < 4; nt++) {
                    mma16816h(acc[mt][nt], ah, bh[nt]);
                    mma16816h(acc[mt][nt], al, bh[nt]);
                }
            }
        }
        __syncthreads();
        if (c + 2 < 32) load_stage(c + 2, st);
    }

    // ---- Epilogue ----
    #pragma unroll
    for (int mt = 0; mt < 4; mt++) {
        #pragma unroll
        for (int half = 0; half < 2; half++) {
            int m = bm + wm + mt * 16 + grp + half * 8;
            #pragma unroll
            for (int nt = 0; nt < 4; nt++) {
                int n = bn + wn + nt * 8 + 2 * tig;
                float v0 = acc[mt][nt][half*2 + 0] + bias[n];
                float v1 = acc[mt][nt][half*2 + 1] + bias[n + 1];
                if (QKV) {
                    int which = n >> 10;
                    int d0 = n & 1023;
                    int h = d0 >> 6, hd = d0 & 63;
                    int b = m >> 11, s = m & 2047;
                    if (which == 2) {
                        size_t o = ((size_t)(b*H_ + h)*HD_ + hd)*S_ + s;
                        g_vT1[o]      = __float2half_rn(v0);
                        g_vT1[o + S_] = __float2half_rn(v1);
                    } else if (which == 1) {
                        size_t o = (((size_t)(b*H_ + h)*S_) + s)*HD_ + hd;
                        *reinterpret_cast<uint32_t*>(g_k1 + o) = pk2hf(v0, v1);
                    } else {
                        size_t o = (((size_t)(b*H_ + h)*S_) + s)*HD_ + hd;
                        fp16 h0,l0,h1,l1;
                        split_h(v0,h0,l0); split_h(v1,h1,l1);
                        *reinterpret_cast<uint32_t*>(g_qhi + o) = pk2h(h0, h1);
                        *reinterpret_cast<uint32_t*>(g_qlo + o) = pk2h(l0, l1);
                    }
                } else {
                    *reinterpret_cast<float2*>(out + (size_t)m * N_TOTAL + n) =
                        make_float2(v0, v1);
                }
            }
        }
    }
}

// ===========================================================================
// Flash attention fp16 2-term: Q (hi/lo) x K (single), P (hi/lo) x V (single).
// Double-buffered K/V cp.async. Stage = K plane + V plane.
// ===========================================================================
#define LDKA 72
#define APLH (64 * LDKA * 2)                  // 9216 bytes per plane
#define STAGE_A (2 * APLH)                    // 18432 (K, V)
#define SMEM_ATTN (2 * STAGE_A)               // 36864
#define OFK 0
#define OFV APLH

__global__ __launch_bounds__(128) void attn_mma()
{
    const int qt = blockIdx.x;
    const int bh = blockIdx.y;
    const int b  = bh >> 4;
    const int h  = bh & 15;
    const size_t head = (size_t)bh * S_ * HD_;

    const int tid = threadIdx.x;
    const int wid = tid >> 5;
    const int lane = tid & 31;
    const int grp = lane >> 2;
    const int tig = lane & 3;
    const int wm = wid * 16;

    const uint32_t sbase = smem_u32(smem_raw);

    auto load_kv = [&](int kt, int st) {
        uint32_t sb = sbase + st * STAGE_A;
        #pragma unroll
        for (int i = 0; i < 4; i++) {
            int idx = tid + i * 128;          // 0..511
            int row = idx >> 3, ch = idx & 7;
            uint32_t so = row * (LDKA*2) + ch * 16;
            size_t gk = head + (size_t)(kt*64 + row) * HD_ + ch * 8;
            size_t gv = head + (size_t)row * S_ + kt*64 + ch * 8;   // vT [hd][s]
            CP16(sb + OFK + so, g_k1 + gk);
            CP16(sb + OFV + so, g_vT1 + gv);
        }
        CP_COMMIT();
    };

    // ---- Q (hi into stage1-K slot, lo into stage1-V slot); prefetch kt=0 ----
    {
        uint32_t sb = sbase + STAGE_A;
        #pragma unroll
        for (int i = 0; i < 4; i++) {
            int idx = tid + i * 128;
            int row = idx >> 3, ch = idx & 7;
            uint32_t so = row * (LDKA*2) + ch * 16;
            size_t g = head + (size_t)(qt*64 + row) * HD_ + ch * 8;
            CP16(sb + OFK + so, g_qhi + g);
            CP16(sb + OFV + so, g_qlo + g);
        }
        CP_COMMIT();
    }
    load_kv(0, 0);
    CP_WAIT1();                               // Q arrived
    __syncthreads();

    uint32_t qh[4][4], ql[4][4];
    {
        const uint32_t* sQhi = reinterpret_cast<const uint32_t*>(smem_raw + STAGE_A + OFK);
        const uint32_t* sQlo = reinterpret_cast<const uint32_t*>(smem_raw + STAGE_A + OFV);
        #pragma unroll
        for (int ks = 0; ks < 4; ks++) {
            int oa  = ((wm + grp) * LDKA + ks*16 + 2*tig) >> 1;
            int oa8 = oa + (8 * LDKA >> 1);
            qh[ks][0] = sQhi[oa];     qh[ks][1] = sQhi[oa8];
            qh[ks][2] = sQhi[oa + 4]; qh[ks][3] = sQhi[oa8 + 4];
            ql[ks][0] = sQlo[oa];     ql[ks][1] = sQlo[oa8];
            ql[ks][2] = sQlo[oa + 4]; ql[ks][3] = sQlo[oa8 + 4];
        }
    }
    __syncthreads();                          // Q consumed; stage 1 reusable

    float o[8][4];
    #pragma unroll
    for (int nt = 0; nt < 8; nt++)
        #pragma unroll
        for (int q = 0; q < 4; q++) o[nt][q] = 0.f;
    float mrow[2] = {-1e30f, -1e30f};
    float lrow[2] = {0.f, 0.f};
    const float scale = 0.125f;

    for (int kt = 0; kt <= qt; kt++) {
        const int st = kt & 1;
        if (kt < qt) { load_kv(kt + 1, st ^ 1); CP_WAIT1(); }
        else         { CP_WAIT0(); }
        __syncthreads();

        const uint32_t* sK32 = reinterpret_cast<const uint32_t*>(smem_raw + st*STAGE_A + OFK);
        const uint32_t* sV32 = reinterpret_cast<const uint32_t*>(smem_raw + st*STAGE_A + OFV);

        // ---- S = Q K^T (2-term) ----
        float s[8][4];
        #pragma unroll
        for (int nt = 0; nt < 8; nt++)
            #pragma unroll
            for (int q = 0; q < 4; q++) s[nt][q] = 0.f;
        #pragma unroll
        for (int nt = 0; nt < 8; nt++) {
            #pragma unroll
            for (int ks = 0; ks < 4; ks++) {
                int ob = ((nt*8 + grp) * LDKA + ks*16 + 2*tig) >> 1;
                uint32_t bf[2];
                bf[0] = sK32[ob]; bf[1] = sK32[ob + 4];
                mma16816h(s[nt], qh[ks], bf);
                mma16816h(s[nt], ql[ks], bf);
            }
        }

        // ---- scale + causal mask ----
        #pragma unroll
        for (int nt = 0; nt < 8; nt++)
            #pragma unroll
            for (int q = 0; q < 4; q++) s[nt][q] *= scale;
        if (kt == qt) {
            #pragma unroll
            for (int nt = 0; nt < 8; nt++) {
                int col = nt * 8 + 2 * tig;
                int r0 = wm + grp, r1 = r0 + 8;
                if (col     > r0) s[nt][0] = -1e30f;
                if (col + 1 > r0) s[nt][1] = -1e30f;
                if (col     > r1) s[nt][2] = -1e30f;
                if (col + 1 > r1) s[nt][3] = -1e30f;
            }
        }

        // ---- online softmax ----
        float mx0 = -1e30f, mx1 = -1e30f;
        #pragma unroll
        for (int nt = 0; nt < 8; nt++) {
            mx0 = fmaxf(mx0, fmaxf(s[nt][0], s[nt][1]));
            mx1 = fmaxf(mx1, fmaxf(s[nt][2], s[nt][3]));
        }
        mx0 = fmaxf(mx0, __shfl_xor_sync(0xffffffffu, mx0, 1));
        mx0 = fmaxf(mx0, __shfl_xor_sync(0xffffffffu, mx0, 2));
        mx1 = fmaxf(mx1, __shfl_xor_sync(0xffffffffu, mx1, 1));
        mx1 = fmaxf(mx1, __shfl_xor_sync(0xffffffffu, mx1, 2));
        float mn0 = fmaxf(mrow[0], mx0);
        float mn1 = fmaxf(mrow[1], mx1);
        float a0 = __expf(mrow[0] - mn0);
        float a1 = __expf(mrow[1] - mn1);
        float sum0 = 0.f, sum1 = 0.f;
        #pragma unroll
        for (int nt = 0; nt < 8; nt++) {
            s[nt][0] = __expf(s[nt][0] - mn0);
            s[nt][1] = __expf(s[nt][1] - mn0);
            s[nt][2] = __expf(s[nt][2] - mn1);
            s[nt][3] = __expf(s[nt][3] - mn1);
            sum0 += s[nt][0] + s[nt][1];
            sum1 += s[nt][2] + s[nt][3];
        }
        sum0 += __shfl_xor_sync(0xffffffffu, sum0, 1);
        sum0 += __shfl_xor_sync(0xffffffffu, sum0, 2);
        sum1 += __shfl_xor_sync(0xffffffffu, sum1, 1);
        sum1 += __shfl_xor_sync(0xffffffffu, sum1, 2);
        lrow[0] = lrow[0] * a0 + sum0;
        lrow[1] = lrow[1] * a1 + sum1;
        mrow[0] = mn0; mrow[1] = mn1;
        #pragma unroll
        for (int nt = 0; nt < 8; nt++) {
            o[nt][0] *= a0; o[nt][1] *= a0;
            o[nt][2] *= a1; o[nt][3] *= a1;
        }

        // ---- pack P (hi + residual lo) ----
        uint32_t ph[4][4], pl[4][4];
        #pragma unroll
        for (int ks = 0; ks < 4; ks++) {
            const float* c0 = s[2*ks];
            const float* c1 = s[2*ks + 1];
            ph[ks][0] = pk2hf(c0[0], c0[1]);
            ph[ks][1] = pk2hf(c0[2], c0[3]);
            ph[ks][2] = pk2hf(c1[0], c1[1]);
            ph[ks][3] = pk2hf(c1[2], c1[3]);
            float r00 = c0[0] - __half2float(__float2half_rn(c0[0]));
            float r01 = c0[1] - __half2float(__float2half_rn(c0[1]));
            float r02 = c0[2] - __half2float(__float2half_rn(c0[2]));
            float r03 = c0[3] - __half2float(__float2half_rn(c0[3]));
            float r10 = c1[0] - __half2float(__float2half_rn(c1[0]));
            float r11 = c1[1] - __half2float(__float2half_rn(c1[1]));
            float r12 = c1[2] - __half2float(__float2half_rn(c1[2]));
            float r13 = c1[3] - __half2float(__float2half_rn(c1[3]));
            pl[ks][0] = pk2hf(r00, r01);
            pl[ks][1] = pk2hf(r02, r03);
            pl[ks][2] = pk2hf(r10, r11);
            pl[ks][3] = pk2hf(r12, r13);
        }

        // ---- O += P V (2-term) ----
        #pragma unroll
        for (int nt = 0; nt < 8; nt++) {
            #pragma unroll
            for (int ks = 0; ks < 4; ks++) {
                int ob = (nt*8 + grp) * (LDKA/2) + ks*8 + tig;
                uint32_t vh[2];
                vh[0] = sV32[ob]; vh[1] = sV32[ob + 4];
                mma16816h(o[nt], ph[ks], vh);
                mma16816h(o[nt], pl[ks], vh);
            }
        }
        __syncthreads();
    }

    // ---- finalize: write y hi/lo planes ----
    float inv0 = 1.0f / lrow[0];
    float inv1 = 1.0f / lrow[1];
    int r0 = qt * 64 + wm + grp;
    int r1 = r0 + 8;
    #pragma unroll
    for (int nt = 0; nt < 8; nt++) {
        int col = h * HD_ + nt * 8 + 2 * tig;
        float y00 = o[nt][0] * inv0, y01 = o[nt][1] * inv0;
        float y10 = o[nt][2] * inv1, y11 = o[nt][3] * inv1;
        fp16 h0,l0,h1,l1;
        size_t o0 = ((size_t)b * S_ + r0) * D_ + col;
        size_t o1 = ((size_t)b * S_ + r1) * D_ + col;
        split_h(y00,h0,l0); split_h(y01,h1,l1);
        *reinterpret_cast<uint32_t*>(g_yhi + o0) = pk2h(h0,h1);
        *reinterpret_cast<uint32_t*>(g_ylo + o0) = pk2h(l0,l1);
        split_h(y10,h0,l0); split_h(y11,h1,l1);
        *reinterpret_cast<uint32_t*>(g_yhi + o1) = pk2h(h0,h1);
        *reinterpret_cast<uint32_t*>(g_ylo + o1) = pk2h(l0,l1);
    }
}

// ---------------------------------------------------------------------------
extern "C" void kernel_launch(void* const* d_in, const int* in_sizes, int n_in,
                              void* d_out, int out_size)
{
    const float* x      = nullptr;
    const float* W_attn = nullptr;
    const float* b_attn = nullptr;
    const float* W_proj = nullptr;
    const float* b_proj = nullptr;
    for (int i = 0; i < n_in; i++) {
        switch (in_sizes[i]) {
            case B_*S_*D_:    x      = (const float*)d_in[i]; break;
            case D_*3*D_:     W_attn = (const float*)d_in[i]; break;
            case 3*D_:        b_attn = (const float*)d_in[i]; break;
            case D_*D_:       W_proj = (const float*)d_in[i]; break;
            case D_:          b_proj = (const float*)d_in[i]; break;
            default: break;
        }
    }
    float* out = (float*)d_out;

    void *xhi, *xlo, *waT, *wpT, *yhi, *ylo;
    cudaGetSymbolAddress(&xhi, g_xhi); cudaGetSymbolAddress(&xlo, g_xlo);
    cudaGetSymbolAddress(&waT, g_waT); cudaGetSymbolAddress(&wpT, g_wpT);
    cudaGetSymbolAddress(&yhi, g_yhi); cudaGetSymbolAddress(&ylo, g_ylo);

    cudaFuncSetAttribute(gemm_mma<N_QKV, true>,
                         cudaFuncAttributeMaxDynamicSharedMemorySize, SMEM_GEMM);
    cudaFuncSetAttribute(gemm_mma<D_, false>,
                         cudaFuncAttributeMaxDynamicSharedMemorySize, SMEM_GEMM);
    cudaFuncSetAttribute(attn_mma,
                         cudaFuncAttributeMaxDynamicSharedMemorySize, SMEM_ATTN);

    conv_split_h<<<(M_*D_/4 + 255)/256, 256>>>(x, (fp16*)xhi, (fp16*)xlo, M_*D_/4);
    conv_wT_h<<<dim3(N_QKV/64, D_/64), 256>>>(W_attn, (fp16*)waT, N_QKV);
    conv_wT_h<<<dim3(D_/64, D_/64), 256>>>(W_proj, (fp16*)wpT, D_);

    dim3 g1(N_QKV / 128, M_ / 128);
    gemm_mma<N_QKV, true><<<g1, 256, SMEM_GEMM>>>(
        (const fp16*)xhi, (const fp16*)xlo, (const fp16*)waT, b_attn, nullptr);

    dim3 g2(S_ / 64, B_ * H_);
    attn_mma<<<g2, 128, SMEM_ATTN>>>();

    dim3 g3(D_ / 128, M_ / 128);
    gemm_mma<D_, false><<<g3, 256, SMEM_GEMM>>>(
        (const fp16*)yhi, (const fp16*)ylo, (const fp16*)wpT, b_proj, out);
}